// round 13
// baseline (speedup 1.0000x reference)
#include <cuda_runtime.h>
#include <cuda_bf16.h>
#include <math.h>
#include <stdint.h>

#define D_MODEL 1024
#define N_HEADS 16
#define D_KV    64
#define INNER   1024
#define QKV_N   3072
#define D_FF    4096
#define SEQ     1024
#define BATCH   2
#define M_ROWS  (BATCH * SEQ)   // 2048
#define TAB_LEN 2047            // rel in [-1023, 1023]

// ---------------- scratch (device globals: no allocation allowed) ----------
__device__ float g_x   [M_ROWS * D_MODEL];
__device__ float g_qkv [M_ROWS * QKV_N];
__device__ float g_ctx [M_ROWS * INNER];
__device__ float g_h   [M_ROWS * D_MODEL];
__device__ float g_y   [M_ROWS * D_MODEL];
__device__ float g_mid [M_ROWS * D_FF];
__device__ float g_bias[N_HEADS * TAB_LEN];
// tf32-rounded weights (wq/wk/wv packed)
__device__ float g_wqkv_r[QKV_N * D_MODEL];
__device__ float g_wo_r  [D_MODEL * INNER];
__device__ float g_wi_r  [D_FF * D_MODEL];
__device__ float g_woff_r[D_MODEL * D_FF];

// ---------------- helpers ----------------------------------------------------
__device__ __forceinline__ float to_tf32(float x) {
    float r;
    asm("cvt.rna.tf32.f32 %0, %1;" : "=f"(r) : "f"(x));
    return r;
}
__device__ __forceinline__ uint32_t smem_u32(const void* p) {
    uint32_t a;
    asm("{ .reg .u64 t; cvta.to.shared.u64 t, %1; cvt.u32.u64 %0, t; }"
        : "=r"(a) : "l"(p));
    return a;
}
#define CP_ASYNC16(sm, gp) \
    asm volatile("cp.async.cg.shared.global [%0], [%1], 16;" :: "r"(sm), "l"(gp))
#define CP_COMMIT() asm volatile("cp.async.commit_group;" ::: "memory")
template <int NN>
__device__ __forceinline__ void cp_wait() {
    asm volatile("cp.async.wait_group %0;" :: "n"(NN) : "memory");
}

__device__ __forceinline__ void mma_tf32u(float* d, const uint32_t* a, const uint32_t* b) {
    asm volatile(
        "mma.sync.aligned.m16n8k8.row.col.f32.tf32.tf32.f32 "
        "{%0,%1,%2,%3}, {%4,%5,%6,%7}, {%8,%9}, {%0,%1,%2,%3};"
        : "+f"(d[0]), "+f"(d[1]), "+f"(d[2]), "+f"(d[3])
        : "r"(a[0]), "r"(a[1]), "r"(a[2]), "r"(a[3]), "r"(b[0]), "r"(b[1]));
}
// tf32 fragment load: 8x4-f32 tile == 8x8-b16 tile; lane l <- (row l/4, col l%4)
__device__ __forceinline__ void ldsm_x4(uint32_t addr, uint32_t* r) {
    asm volatile("ldmatrix.sync.aligned.m8n8.x4.shared.b16 {%0,%1,%2,%3}, [%4];"
        : "=r"(r[0]), "=r"(r[1]), "=r"(r[2]), "=r"(r[3]) : "r"(addr));
}

// ---------------- fused weight rounding (one launch) ------------------------
#define N4S ((INNER * D_MODEL) / 4)
#define N4B ((D_FF * D_MODEL) / 4)
#define N4TOT (4 * N4S + 2 * N4B)
__global__ void round_all_kernel(const float4* __restrict__ wq,
                                 const float4* __restrict__ wk,
                                 const float4* __restrict__ wv,
                                 const float4* __restrict__ wo,
                                 const float4* __restrict__ wi,
                                 const float4* __restrict__ woff,
                                 float4* __restrict__ dqkv,
                                 float4* __restrict__ dwo,
                                 float4* __restrict__ dwi,
                                 float4* __restrict__ dwoff) {
    int i = blockIdx.x * blockDim.x + threadIdx.x;
    if (i >= N4TOT) return;
    const float4* src;
    float4* dst;
    int off;
    if (i < 3 * N4S)      { int s = i / N4S; off = i - s * N4S;
                            src = (s == 0) ? wq : (s == 1) ? wk : wv;
                            dst = dqkv + (size_t)s * N4S; }
    else if (i < 4 * N4S) { off = i - 3 * N4S; src = wo;   dst = dwo; }
    else if (i < 4 * N4S + N4B) { off = i - 4 * N4S; src = wi; dst = dwi; }
    else                  { off = i - 4 * N4S - N4B; src = woff; dst = dwoff; }
    float4 v = src[off];
    v.x = to_tf32(v.x); v.y = to_tf32(v.y);
    v.z = to_tf32(v.z); v.w = to_tf32(v.w);
    dst[off] = v;
}

// ---------------- RMSNorm (T5), output rounded to tf32 ----------------------
__global__ void rmsnorm_kernel(const float* __restrict__ in,
                               const float* __restrict__ w,
                               float* __restrict__ out) {
    int row = blockIdx.x;
    const float4* inr = (const float4*)(in + (size_t)row * D_MODEL);
    float4 v = inr[threadIdx.x];
    float ss = v.x * v.x + v.y * v.y + v.z * v.z + v.w * v.w;
    #pragma unroll
    for (int o = 16; o; o >>= 1) ss += __shfl_xor_sync(0xFFFFFFFFu, ss, o);
    __shared__ float sred[8];
    if ((threadIdx.x & 31) == 0) sred[threadIdx.x >> 5] = ss;
    __syncthreads();
    float total = 0.f;
    #pragma unroll
    for (int i = 0; i < 8; i++) total += sred[i];
    float scale = rsqrtf(total * (1.0f / D_MODEL) + 1e-6f);
    float4 wv = ((const float4*)w)[threadIdx.x];
    float4 o4 = make_float4(to_tf32(v.x * scale * wv.x), to_tf32(v.y * scale * wv.y),
                            to_tf32(v.z * scale * wv.z), to_tf32(v.w * scale * wv.w));
    ((float4*)(out + (size_t)row * D_MODEL))[threadIdx.x] = o4;
}

// ---------------- relative position bias table ------------------------------
__global__ void bias_table_kernel(const float* __restrict__ rel_bias,
                                  float* __restrict__ tab) {
    int i = blockIdx.x * blockDim.x + threadIdx.x;
    if (i >= TAB_LEN) return;
    int rel = i - 1023;
    int rb = (rel > 0) ? 16 : 0;
    int rp = rel < 0 ? -rel : rel;
    int val;
    if (rp < 8) {
        val = rp;
    } else {
        float t = logf((float)rp * 0.125f) * (8.0f / 2.772588722239781f);
        int large = 8 + (int)t;
        val = large < 15 ? large : 15;
    }
    int bucket = rb + val;
    #pragma unroll
    for (int h = 0; h < N_HEADS; h++)
        tab[h * TAB_LEN + i] = rel_bias[bucket * N_HEADS + h];
}

// ---------------- tf32 mma GEMM: 4 warps x 64x64 tiles, 3-stage cp.async ----
// C[M,N] = A[M,K] @ W[N,K]^T. Inputs pre-rounded to tf32.
// EPI: 1 = relu + round, 3 = atomicAdd (split-K), 4 = round.
#define SPITCH 36
#define TILEF  (128 * SPITCH)
#define BUFF   (2 * TILEF)
#define GEMM_SMEM (3 * BUFF * 4)       // 110592 bytes (3 stages)

template <int EPI>
__global__ __launch_bounds__(128, 2)
void gemm_tf32_kernel(const float* __restrict__ A, const float* __restrict__ W,
                      float* __restrict__ C, int M, int Nc, int Kstride, int Klen) {
    extern __shared__ float sm[];
    const int tid = threadIdx.x;
    const int wid = tid >> 5, lid = tid & 31;
    const int gid = lid >> 2, tig = lid & 3;
    const int wm = wid >> 1, wn = wid & 1;   // 2 x 2 warp grid, 64x64 tiles
    const int m0 = blockIdx.y * 128;
    const int n0 = blockIdx.x * 128;
    const int kbase = blockIdx.z * Klen;
    const int T = Klen >> 5;

    float acc[4][8][4];
    #pragma unroll
    for (int i = 0; i < 4; i++)
        #pragma unroll
        for (int j = 0; j < 8; j++)
            #pragma unroll
            for (int c = 0; c < 4; c++) acc[i][j][c] = 0.f;

    const uint32_t smb = smem_u32(sm);

    const int lg = lid >> 3, r8 = lid & 7;
    // A tiles for (mi,ks): lane-groups -> m0-7/klo, m8-15/klo, m0-7/khi, m8-15/khi
    const uint32_t aoff = ((uint32_t)(wm * 64 + (lg & 1) * 8 + r8) * SPITCH
                           + (lg >> 1) * 4) * 4;
    // B tiles for nj-pair p: lane-groups -> n0-7/klo, n0-7/khi, n8-15/klo, n8-15/khi
    const uint32_t boff = ((uint32_t)(wn * 64 + (lg >> 1) * 8 + r8) * SPITCH
                           + (lg & 1) * 4) * 4 + (uint32_t)TILEF * 4;

    auto load_tiles = [&](int buf, int k0) {
        uint32_t base = smb + (uint32_t)buf * (BUFF * 4);
        #pragma unroll
        for (int t = 0; t < 8; t++) {
            int c = tid + t * 128;             // 0..1023
            int row = c >> 3;
            int cb = (c & 7) * 16;
            uint32_t soff = (uint32_t)row * (SPITCH * 4) + cb;
            CP_ASYNC16(base + soff,
                       A + (size_t)(m0 + row) * Kstride + kbase + k0 + (cb >> 2));
            CP_ASYNC16(base + (uint32_t)(TILEF * 4) + soff,
                       W + (size_t)(n0 + row) * Kstride + kbase + k0 + (cb >> 2));
        }
    };

    load_tiles(0, 0);
    CP_COMMIT();
    load_tiles(1, 32);
    CP_COMMIT();

    int stage = 0;
    for (int i = 0; i < T; i++) {
        if (i < T - 1) cp_wait<1>(); else cp_wait<0>();
        __syncthreads();
        if (i + 2 < T) {
            int nst = stage + 2; if (nst >= 3) nst -= 3;
            load_tiles(nst, (i + 2) << 5);
            CP_COMMIT();
        }

        const uint32_t base = smb + (uint32_t)stage * (BUFF * 4);
        #pragma unroll
        for (int ks = 0; ks < 4; ks++) {
            const uint32_t kso = (uint32_t)(ks * 8) * 4;
            uint32_t a[4][4], bb[4][4];
            #pragma unroll
            for (int mi = 0; mi < 4; mi++)
                ldsm_x4(base + aoff + (uint32_t)(mi * 16 * SPITCH) * 4 + kso, a[mi]);
            #pragma unroll
            for (int p = 0; p < 4; p++)
                ldsm_x4(base + boff + (uint32_t)(p * 16 * SPITCH) * 4 + kso, bb[p]);
            #pragma unroll
            for (int mi = 0; mi < 4; mi++)
                #pragma unroll
                for (int p = 0; p < 4; p++) {
                    mma_tf32u(acc[mi][2 * p], a[mi], bb[p]);
                    mma_tf32u(acc[mi][2 * p + 1], a[mi], bb[p] + 2);
                }
        }
        stage = (stage + 1 == 3) ? 0 : stage + 1;
    }

    #pragma unroll
    for (int mi = 0; mi < 4; mi++) {
        const int mA = m0 + wm * 64 + mi * 16 + gid;
        const int mB = mA + 8;
        #pragma unroll
        for (int nj = 0; nj < 8; nj++) {
            const int col = n0 + wn * 64 + nj * 8 + tig * 2;
            float2 v0 = make_float2(acc[mi][nj][0], acc[mi][nj][1]);
            float2 v1 = make_float2(acc[mi][nj][2], acc[mi][nj][3]);
            if (EPI == 1) {
                v0.x = to_tf32(fmaxf(v0.x, 0.f)); v0.y = to_tf32(fmaxf(v0.y, 0.f));
                v1.x = to_tf32(fmaxf(v1.x, 0.f)); v1.y = to_tf32(fmaxf(v1.y, 0.f));
            } else if (EPI == 4) {
                v0.x = to_tf32(v0.x); v0.y = to_tf32(v0.y);
                v1.x = to_tf32(v1.x); v1.y = to_tf32(v1.y);
            }
            if (EPI == 3) {
                float* c0 = C + (size_t)mA * Nc + col;
                float* c1 = C + (size_t)mB * Nc + col;
                atomicAdd(c0, v0.x); atomicAdd(c0 + 1, v0.y);
                atomicAdd(c1, v1.x); atomicAdd(c1 + 1, v1.y);
            } else {
                *(float2*)(C + (size_t)mA * Nc + col) = v0;
                *(float2*)(C + (size_t)mB * Nc + col) = v1;
            }
        }
    }
}

// ---------------- tensor-core flash attention (tf32 mma + ldmatrix) ---------
#define KPITCH 68
#define VPITCH 72
#define PPITCH 68
#define KBUF (64 * KPITCH)
#define VBUF (64 * VPITCH)
#define ATT_SMEM ((2 * KBUF + 2 * VBUF + 64 * PPITCH) * 4)  // 89088 B

__global__ __launch_bounds__(128, 2)
void attention_mma_kernel(const float* __restrict__ QKV,
                          const float* __restrict__ tab,
                          float* __restrict__ O) {
    extern __shared__ float smem[];
    const float* Vbp[2] = {smem + 2 * KBUF, smem + 2 * KBUF + VBUF};
    float* Ps = smem + 2 * KBUF + 2 * VBUF;

    const int bh = blockIdx.y;
    const int b = bh >> 4, h = bh & 15;
    const int q0 = blockIdx.x * 64;
    const int tid = threadIdx.x;
    const int wid = tid >> 5, lid = tid & 31;
    const int gid = lid >> 2, tig = lid & 3;
    const int lg = lid >> 3, r8 = lid & 7;
    const uint32_t smb = smem_u32(smem);

    const uint32_t kboff = ((uint32_t)((lg >> 1) * 8 + r8) * KPITCH + (lg & 1) * 4) * 4;
    const uint32_t paoff = smb
        + ((uint32_t)(wid * 16 + (lg & 1) * 8 + r8) * PPITCH + (lg >> 1) * 4) * 4
        + (uint32_t)(2 * KBUF + 2 * VBUF) * 4;

    uint32_t qfu[8][4];
    {
        const float* Qb = QKV + (size_t)(b * SEQ + q0 + wid * 16 + gid) * QKV_N + h * D_KV;
        #pragma unroll
        for (int k = 0; k < 8; k++) {
            qfu[k][0] = __float_as_uint(Qb[k * 8 + tig]);
            qfu[k][1] = __float_as_uint(Qb[8 * QKV_N + k * 8 + tig]);
            qfu[k][2] = __float_as_uint(Qb[k * 8 + tig + 4]);
            qfu[k][3] = __float_as_uint(Qb[8 * QKV_N + k * 8 + tig + 4]);
        }
    }

    auto load_kv = [&](int buf, int k0) {
        const float* Kg = QKV + INNER + h * D_KV;
        const float* Vg = QKV + 2 * INNER + h * D_KV;
        uint32_t kb = smb + (uint32_t)(buf * KBUF) * 4;
        uint32_t vb = smb + (uint32_t)(2 * KBUF + buf * VBUF) * 4;
        #pragma unroll
        for (int t = 0; t < 8; t++) {
            int idx = tid + t * 128;
            int row = idx >> 4;
            int c4 = (idx & 15) * 4;
            size_t gaddr = (size_t)(b * SEQ + k0 + row) * QKV_N + c4;
            CP_ASYNC16(kb + (uint32_t)(row * KPITCH + c4) * 4, Kg + gaddr);
            CP_ASYNC16(vb + (uint32_t)(row * VPITCH + c4) * 4, Vg + gaddr);
        }
    };

    float oacc[8][4];
    #pragma unroll
    for (int nj = 0; nj < 8; nj++)
        #pragma unroll
        for (int c = 0; c < 4; c++) oacc[nj][c] = 0.f;
    float m0 = -1e30f, m1 = -1e30f, l0 = 0.f, l1 = 0.f;

    load_kv(0, 0);
    CP_COMMIT();

    for (int it = 0; it < SEQ / 64; it++) {
        const int cur = it & 1;
        const int k0 = it * 64;
        cp_wait<0>();
        __syncthreads();
        if (it + 1 < SEQ / 64) {
            load_kv(cur ^ 1, k0 + 64);
            CP_COMMIT();
        }
        const uint32_t kbase = smb + (uint32_t)(cur * KBUF) * 4;
        const float* Vs = Vbp[cur];

        float sacc[8][4];
        #pragma unroll
        for (int nj = 0; nj < 8; nj++)
            #pragma unroll
            for (int c = 0; c < 4; c++) sacc[nj][c] = 0.f;
        #pragma unroll
        for (int ks = 0; ks < 8; ks++) {
            const uint32_t kso = (uint32_t)(ks * 8) * 4;
            uint32_t bb[4][4];
            #pragma unroll
            for (int p = 0; p < 4; p++)
                ldsm_x4(kbase + kboff + (uint32_t)(p * 16 * KPITCH) * 4 + kso, bb[p]);
            #pragma unroll
            for (int p = 0; p < 4; p++) {
                mma_tf32u(sacc[2 * p], qfu[ks], bb[p]);
                mma_tf32u(sacc[2 * p + 1], qfu[ks], bb[p] + 2);
            }
        }

        const float* bt = tab + h * TAB_LEN + 1023 + k0 - (q0 + wid * 16);
        float rx0 = -1e30f, rx1 = -1e30f;
        #pragma unroll
        for (int nj = 0; nj < 8; nj++) {
            int c = nj * 8 + 2 * tig;
            sacc[nj][0] += __ldg(bt + c - gid);
            sacc[nj][1] += __ldg(bt + c + 1 - gid);
            sacc[nj][2] += __ldg(bt + c - gid - 8);
            sacc[nj][3] += __ldg(bt + c + 1 - gid - 8);
            rx0 = fmaxf(rx0, fmaxf(sacc[nj][0], sacc[nj][1]));
            rx1 = fmaxf(rx1, fmaxf(sacc[nj][2], sacc[nj][3]));
        }
        rx0 = fmaxf(rx0, __shfl_xor_sync(0xFFFFFFFFu, rx0, 1));
        rx0 = fmaxf(rx0, __shfl_xor_sync(0xFFFFFFFFu, rx0, 2));
        rx1 = fmaxf(rx1, __shfl_xor_sync(0xFFFFFFFFu, rx1, 1));
        rx1 = fmaxf(rx1, __shfl_xor_sync(0xFFFFFFFFu, rx1, 2));
        float mn0 = fmaxf(m0, rx0), mn1 = fmaxf(m1, rx1);
        float sc0 = __expf(m0 - mn0), sc1 = __expf(m1 - mn1);
        m0 = mn0; m1 = mn1;

        float rs0 = 0.f, rs1 = 0.f;
        float* pw0 = Ps + (wid * 16 + gid) * PPITCH;
        float* pw1 = pw0 + 8 * PPITCH;
        #pragma unroll
        for (int nj = 0; nj < 8; nj++) {
            int c = nj * 8 + 2 * tig;
            float p0 = __expf(sacc[nj][0] - m0);
            float p1 = __expf(sacc[nj][1] - m0);
            float p2 = __expf(sacc[nj][2] - m1);
            float p3 = __expf(sacc[nj][3] - m1);
            rs0 += p0 + p1; rs1 += p2 + p3;
            *(float2*)(pw0 + c) = make_float2(to_tf32(p0), to_tf32(p1));
            *(float2*)(pw1 + c) = make_float2(to_tf32(p2), to_tf32(p3));
        }
        rs0 += __shfl_xor_sync(0xFFFFFFFFu, rs0, 1);
        rs0 += __shfl_xor_sync(0xFFFFFFFFu, rs0, 2);
        rs1 += __shfl_xor_sync(0xFFFFFFFFu, rs1, 1);
        rs1 += __shfl_xor_sync(0xFFFFFFFFu, rs1, 2);
        l0 = l0 * sc0 + rs0;
        l1 = l1 * sc1 + rs1;
        #pragma unroll
        for (int nj = 0; nj < 8; nj++) {
            oacc[nj][0] *= sc0; oacc[nj][1] *= sc0;
            oacc[nj][2] *= sc1; oacc[nj][3] *= sc1;
        }
        __syncwarp();

        #pragma unroll
        for (int k = 0; k < 8; k++) {
            uint32_t af[4];
            ldsm_x4(paoff + (uint32_t)(k * 8) * 4, af);
            #pragma unroll
            for (int nj = 0; nj < 8; nj++) {
                float bf[2];
                const float* vp = Vs + (k * 8 + tig) * VPITCH + nj * 8 + gid;
                bf[0] = vp[0];
                bf[1] = vp[4 * VPITCH];
                mma_tf32u(oacc[nj], af, (const uint32_t*)bf);
            }
        }
    }

    float i0 = 1.f / l0, i1 = 1.f / l1;
    float* ob = O + (size_t)(b * SEQ + q0 + wid * 16 + gid) * INNER + h * D_KV;
    #pragma unroll
    for (int nj = 0; nj < 8; nj++) {
        int c = nj * 8 + 2 * tig;
        *(float2*)(ob + c) = make_float2(to_tf32(oacc[nj][0] * i0),
                                         to_tf32(oacc[nj][1] * i0));
        *(float2*)(ob + 8 * INNER + c) = make_float2(to_tf32(oacc[nj][2] * i1),
                                                     to_tf32(oacc[nj][3] * i1));
    }
}

// ---------------- launch -----------------------------------------------------
extern "C" void kernel_launch(void* const* d_in, const int* in_sizes, int n_in,
                              void* d_out, int out_size) {
    const float* hidden  = (const float*)d_in[0];
    const float* ln1_w   = (const float*)d_in[1];
    const float* wq      = (const float*)d_in[2];
    const float* wk      = (const float*)d_in[3];
    const float* wv      = (const float*)d_in[4];
    const float* wo      = (const float*)d_in[5];
    const float* relbias = (const float*)d_in[6];
    const float* ln2_w   = (const float*)d_in[7];
    const float* wi      = (const float*)d_in[8];
    const float* wo_ff   = (const float*)d_in[9];
    float* out = (float*)d_out;

    float *px, *pqkv, *pctx, *ph, *py, *pmid, *pbias;
    float *pwqkv, *pwo, *pwi, *pwoff;
    cudaGetSymbolAddress((void**)&px,    g_x);
    cudaGetSymbolAddress((void**)&pqkv,  g_qkv);
    cudaGetSymbolAddress((void**)&pctx,  g_ctx);
    cudaGetSymbolAddress((void**)&ph,    g_h);
    cudaGetSymbolAddress((void**)&py,    g_y);
    cudaGetSymbolAddress((void**)&pmid,  g_mid);
    cudaGetSymbolAddress((void**)&pbias, g_bias);
    cudaGetSymbolAddress((void**)&pwqkv, g_wqkv_r);
    cudaGetSymbolAddress((void**)&pwo,   g_wo_r);
    cudaGetSymbolAddress((void**)&pwi,   g_wi_r);
    cudaGetSymbolAddress((void**)&pwoff, g_woff_r);

    cudaFuncSetAttribute(gemm_tf32_kernel<1>, cudaFuncAttributeMaxDynamicSharedMemorySize, GEMM_SMEM);
    cudaFuncSetAttribute(gemm_tf32_kernel<3>, cudaFuncAttributeMaxDynamicSharedMemorySize, GEMM_SMEM);
    cudaFuncSetAttribute(gemm_tf32_kernel<4>, cudaFuncAttributeMaxDynamicSharedMemorySize, GEMM_SMEM);
    cudaFuncSetAttribute(attention_mma_kernel, cudaFuncAttributeMaxDynamicSharedMemorySize, ATT_SMEM);

    // 0: fused weight rounding
    round_all_kernel<<<(N4TOT + 255) / 256, 256>>>(
        (const float4*)wq, (const float4*)wk, (const float4*)wv,
        (const float4*)wo, (const float4*)wi, (const float4*)wo_ff,
        (float4*)pwqkv, (float4*)pwo, (float4*)pwi, (float4*)pwoff);

    // 1,2
    bias_table_kernel<<<(TAB_LEN + 255) / 256, 256>>>(relbias, pbias);
    rmsnorm_kernel<<<M_ROWS, 256>>>(hidden, ln1_w, px);

    // 3: QKV projection (rounded output)
    gemm_tf32_kernel<4><<<dim3(QKV_N / 128, M_ROWS / 128), 128, GEMM_SMEM>>>(
        px, pwqkv, pqkv, M_ROWS, QKV_N, D_MODEL, D_MODEL);

    // 4: attention
    attention_mma_kernel<<<dim3(SEQ / 64, BATCH * N_HEADS), 128, ATT_SMEM>>>(
        pqkv, pbias, pctx);

    // 5 (ncu target): h = hidden + ctx @ wo^T (split-K2 atomic)
    cudaMemcpyAsync(ph, hidden, (size_t)M_ROWS * D_MODEL * sizeof(float),
                    cudaMemcpyDeviceToDevice);
    gemm_tf32_kernel<3><<<dim3(D_MODEL / 128, M_ROWS / 128, 2), 128, GEMM_SMEM>>>(
        pctx, pwo, ph, M_ROWS, D_MODEL, INNER, INNER / 2);

    // 6
    rmsnorm_kernel<<<M_ROWS, 256>>>(ph, ln2_w, py);

    // 7: mid = relu(y @ wi^T)
    gemm_tf32_kernel<1><<<dim3(D_FF / 128, M_ROWS / 128), 128, GEMM_SMEM>>>(
        py, pwi, pmid, M_ROWS, D_FF, D_MODEL, D_MODEL);

    // 8: out = h + mid @ wo_ff^T (split-K2 atomic)
    cudaMemcpyAsync(out, ph, (size_t)M_ROWS * D_MODEL * sizeof(float),
                    cudaMemcpyDeviceToDevice);
    gemm_tf32_kernel<3><<<dim3(D_MODEL / 128, M_ROWS / 128, 2), 128, GEMM_SMEM>>>(
        pmid, pwoff, out, M_ROWS, D_MODEL, D_FF, D_FF / 2);
}

// round 14
// speedup vs baseline: 1.4062x; 1.4062x over previous
#include <cuda_runtime.h>
#include <cuda_fp16.h>
#include <math.h>
#include <stdint.h>

#define D_MODEL 1024
#define N_HEADS 16
#define D_KV    64
#define INNER   1024
#define QKV_N   3072
#define D_FF    4096
#define SEQ     1024
#define BATCH   2
#define M_ROWS  (BATCH * SEQ)   // 2048
#define TAB_LEN 2047            // rel in [-1023, 1023]

// ---------------- scratch (device globals: no allocation allowed) ----------
__device__ __half g_x   [M_ROWS * D_MODEL];
__device__ float  g_qkv [M_ROWS * QKV_N];
__device__ __half g_ctx [M_ROWS * INNER];
__device__ float  g_h   [M_ROWS * D_MODEL];
__device__ __half g_y   [M_ROWS * D_MODEL];
__device__ __half g_mid [M_ROWS * D_FF];
__device__ float  g_bias[N_HEADS * TAB_LEN];
// fp16 weights (wq/wk/wv packed)
__device__ __half g_wqkv_h[QKV_N * D_MODEL];
__device__ __half g_wo_h  [D_MODEL * INNER];
__device__ __half g_wi_h  [D_FF * D_MODEL];
__device__ __half g_woff_h[D_MODEL * D_FF];

// ---------------- helpers ----------------------------------------------------
__device__ __forceinline__ float to_tf32(float x) {
    float r;
    asm("cvt.rna.tf32.f32 %0, %1;" : "=f"(r) : "f"(x));
    return r;
}
__device__ __forceinline__ uint32_t smem_u32(const void* p) {
    uint32_t a;
    asm("{ .reg .u64 t; cvta.to.shared.u64 t, %1; cvt.u32.u64 %0, t; }"
        : "=r"(a) : "l"(p));
    return a;
}
#define CP_ASYNC16(sm, gp) \
    asm volatile("cp.async.cg.shared.global [%0], [%1], 16;" :: "r"(sm), "l"(gp))
#define CP_COMMIT() asm volatile("cp.async.commit_group;" ::: "memory")
template <int NN>
__device__ __forceinline__ void cp_wait() {
    asm volatile("cp.async.wait_group %0;" :: "n"(NN) : "memory");
}

// fp16 mma: m16n8k16, fp32 accumulate
__device__ __forceinline__ void mma_f16(float* d, const uint32_t* a, const uint32_t* b) {
    asm volatile(
        "mma.sync.aligned.m16n8k16.row.col.f32.f16.f16.f32 "
        "{%0,%1,%2,%3}, {%4,%5,%6,%7}, {%8,%9}, {%0,%1,%2,%3};"
        : "+f"(d[0]), "+f"(d[1]), "+f"(d[2]), "+f"(d[3])
        : "r"(a[0]), "r"(a[1]), "r"(a[2]), "r"(a[3]), "r"(b[0]), "r"(b[1]));
}
// tf32 mma (attention)
__device__ __forceinline__ void mma_tf32u(float* d, const uint32_t* a, const uint32_t* b) {
    asm volatile(
        "mma.sync.aligned.m16n8k8.row.col.f32.tf32.tf32.f32 "
        "{%0,%1,%2,%3}, {%4,%5,%6,%7}, {%8,%9}, {%0,%1,%2,%3};"
        : "+f"(d[0]), "+f"(d[1]), "+f"(d[2]), "+f"(d[3])
        : "r"(a[0]), "r"(a[1]), "r"(a[2]), "r"(a[3]), "r"(b[0]), "r"(b[1]));
}
__device__ __forceinline__ void ldsm_x4(uint32_t addr, uint32_t* r) {
    asm volatile("ldmatrix.sync.aligned.m8n8.x4.shared.b16 {%0,%1,%2,%3}, [%4];"
        : "=r"(r[0]), "=r"(r[1]), "=r"(r[2]), "=r"(r[3]) : "r"(addr));
}

// ---------------- fused weight conversion to fp16 (one launch) --------------
#define N4S ((INNER * D_MODEL) / 4)
#define N4B ((D_FF * D_MODEL) / 4)
#define N4TOT (4 * N4S + 2 * N4B)
__global__ void convert_all_kernel(const float4* __restrict__ wq,
                                   const float4* __restrict__ wk,
                                   const float4* __restrict__ wv,
                                   const float4* __restrict__ wo,
                                   const float4* __restrict__ wi,
                                   const float4* __restrict__ woff,
                                   __half* __restrict__ dqkv,
                                   __half* __restrict__ dwo,
                                   __half* __restrict__ dwi,
                                   __half* __restrict__ dwoff) {
    int i = blockIdx.x * blockDim.x + threadIdx.x;
    if (i >= N4TOT) return;
    const float4* src;
    __half* dst;
    int off;
    if (i < 3 * N4S)      { int s = i / N4S; off = i - s * N4S;
                            src = (s == 0) ? wq : (s == 1) ? wk : wv;
                            dst = dqkv + (size_t)s * (INNER * D_MODEL); }
    else if (i < 4 * N4S) { off = i - 3 * N4S; src = wo;   dst = dwo; }
    else if (i < 4 * N4S + N4B) { off = i - 4 * N4S; src = wi; dst = dwi; }
    else                  { off = i - 4 * N4S - N4B; src = woff; dst = dwoff; }
    float4 v = src[off];
    __half2* d2 = (__half2*)(dst) + off * 2;
    d2[0] = __floats2half2_rn(v.x, v.y);
    d2[1] = __floats2half2_rn(v.z, v.w);
}

// ---------------- RMSNorm (T5), output fp16 ----------------------------------
__global__ void rmsnorm_kernel(const float* __restrict__ in,
                               const float* __restrict__ w,
                               __half* __restrict__ out) {
    int row = blockIdx.x;
    const float4* inr = (const float4*)(in + (size_t)row * D_MODEL);
    float4 v = inr[threadIdx.x];
    float ss = v.x * v.x + v.y * v.y + v.z * v.z + v.w * v.w;
    #pragma unroll
    for (int o = 16; o; o >>= 1) ss += __shfl_xor_sync(0xFFFFFFFFu, ss, o);
    __shared__ float sred[8];
    if ((threadIdx.x & 31) == 0) sred[threadIdx.x >> 5] = ss;
    __syncthreads();
    float total = 0.f;
    #pragma unroll
    for (int i = 0; i < 8; i++) total += sred[i];
    float scale = rsqrtf(total * (1.0f / D_MODEL) + 1e-6f);
    float4 wv = ((const float4*)w)[threadIdx.x];
    __half2* o2 = (__half2*)(out + (size_t)row * D_MODEL) + threadIdx.x * 2;
    o2[0] = __floats2half2_rn(v.x * scale * wv.x, v.y * scale * wv.y);
    o2[1] = __floats2half2_rn(v.z * scale * wv.z, v.w * scale * wv.w);
}

// ---------------- relative position bias table ------------------------------
__global__ void bias_table_kernel(const float* __restrict__ rel_bias,
                                  float* __restrict__ tab) {
    int i = blockIdx.x * blockDim.x + threadIdx.x;
    if (i >= TAB_LEN) return;
    int rel = i - 1023;
    int rb = (rel > 0) ? 16 : 0;
    int rp = rel < 0 ? -rel : rel;
    int val;
    if (rp < 8) {
        val = rp;
    } else {
        float t = logf((float)rp * 0.125f) * (8.0f / 2.772588722239781f);
        int large = 8 + (int)t;
        val = large < 15 ? large : 15;
    }
    int bucket = rb + val;
    #pragma unroll
    for (int h = 0; h < N_HEADS; h++)
        tab[h * TAB_LEN + i] = rel_bias[bucket * N_HEADS + h];
}

// ---------------- fp16 mma GEMM: 8 warps x 64x32 tiles, 3-stage cp.async ----
// C[M,N] = A[M,K] @ W[N,K]^T. A,W fp16. Accumulate fp32.
// EPI: 1 = relu -> fp16 C, 3 = atomicAdd fp32 C (split-K), 4 = tf32-round fp32 C.
#define HPITCH 40                      // fp16 per row (80 B): r*20 mod 32 covers banks
#define TILEH  (128 * HPITCH)          // 5120 halves per tile
#define BUFFH  (2 * TILEH)             // A+B = 10240 halves = 20480 B
#define GEMM_SMEM (3 * BUFFH * 2)      // 61440 bytes (3 stages)

template <int EPI, typename CT>
__global__ __launch_bounds__(256, 2)
void gemm_f16_kernel(const __half* __restrict__ A, const __half* __restrict__ W,
                     CT* __restrict__ C, int M, int Nc, int Kstride, int Klen) {
    extern __shared__ __half smh[];
    const int tid = threadIdx.x;
    const int wid = tid >> 5, lid = tid & 31;
    const int gid = lid >> 2, tig = lid & 3;
    const int wm = wid >> 2, wn = wid & 3;   // 2 x 4 warp grid, 64x32 tiles
    const int m0 = blockIdx.y * 128;
    const int n0 = blockIdx.x * 128;
    const int kbase = blockIdx.z * Klen;
    const int T = Klen >> 5;                 // chunks of 32 fp16

    float acc[4][4][4];
    #pragma unroll
    for (int i = 0; i < 4; i++)
        #pragma unroll
        for (int j = 0; j < 4; j++)
            #pragma unroll
            for (int c = 0; c < 4; c++) acc[i][j][c] = 0.f;

    const uint32_t smb = smem_u32(smh);

    const int lg = lid >> 3, r8 = lid & 7;
    // A x4 tiles: (m0-7,klo),(m8-15,klo),(m0-7,khi),(m8-15,khi)
    const uint32_t aoff = ((uint32_t)(wm * 64 + (lg & 1) * 8 + r8) * HPITCH
                           + (lg >> 1) * 8) * 2;
    // B x4 tiles: (n0-7,klo),(n0-7,khi),(n8-15,klo),(n8-15,khi)
    const uint32_t boff = ((uint32_t)(wn * 32 + (lg >> 1) * 8 + r8) * HPITCH
                           + (lg & 1) * 8) * 2 + (uint32_t)TILEH * 2;

    auto load_tiles = [&](int buf, int k0) {
        uint32_t base = smb + (uint32_t)buf * (BUFFH * 2);
        #pragma unroll
        for (int t = 0; t < 2; t++) {
            int c = tid + t * 256;               // 0..511
            int row = c >> 2;
            int ch = (c & 3) * 8;                // fp16 elem offset in row
            uint32_t soff = (uint32_t)row * (HPITCH * 2) + ch * 2;
            CP_ASYNC16(base + soff,
                       A + (size_t)(m0 + row) * Kstride + kbase + k0 + ch);
            CP_ASYNC16(base + (uint32_t)TILEH * 2 + soff,
                       W + (size_t)(n0 + row) * Kstride + kbase + k0 + ch);
        }
    };

    load_tiles(0, 0);
    CP_COMMIT();
    load_tiles(1, 32);
    CP_COMMIT();

    int stage = 0;
    for (int i = 0; i < T; i++) {
        if (i < T - 1) cp_wait<1>(); else cp_wait<0>();
        __syncthreads();
        if (i + 2 < T) {
            int nst = stage + 2; if (nst >= 3) nst -= 3;
            load_tiles(nst, (i + 2) << 5);
            CP_COMMIT();
        }

        const uint32_t base = smb + (uint32_t)stage * (BUFFH * 2);
        #pragma unroll
        for (int kh = 0; kh < 2; kh++) {         // two k16 steps per 32-chunk
            const uint32_t kso = (uint32_t)kh * 32;  // 16 fp16 = 32 B
            uint32_t a[4][4], bb[2][4];
            #pragma unroll
            for (int mi = 0; mi < 4; mi++)
                ldsm_x4(base + aoff + (uint32_t)(mi * 16 * HPITCH) * 2 + kso, a[mi]);
            #pragma unroll
            for (int p = 0; p < 2; p++)
                ldsm_x4(base + boff + (uint32_t)(p * 16 * HPITCH) * 2 + kso, bb[p]);
            #pragma unroll
            for (int mi = 0; mi < 4; mi++) {
                mma_f16(acc[mi][0], a[mi], bb[0]);
                mma_f16(acc[mi][1], a[mi], bb[0] + 2);
                mma_f16(acc[mi][2], a[mi], bb[1]);
                mma_f16(acc[mi][3], a[mi], bb[1] + 2);
            }
        }
        stage = (stage + 1 == 3) ? 0 : stage + 1;
    }

    #pragma unroll
    for (int mi = 0; mi < 4; mi++) {
        const int mA = m0 + wm * 64 + mi * 16 + gid;
        const int mB = mA + 8;
        #pragma unroll
        for (int nj = 0; nj < 4; nj++) {
            const int col = n0 + wn * 32 + nj * 8 + tig * 2;
            float2 v0 = make_float2(acc[mi][nj][0], acc[mi][nj][1]);
            float2 v1 = make_float2(acc[mi][nj][2], acc[mi][nj][3]);
            if (EPI == 1) {       // relu -> fp16
                __half2* c0 = (__half2*)((__half*)C + (size_t)mA * Nc + col);
                __half2* c1 = (__half2*)((__half*)C + (size_t)mB * Nc + col);
                *c0 = __floats2half2_rn(fmaxf(v0.x, 0.f), fmaxf(v0.y, 0.f));
                *c1 = __floats2half2_rn(fmaxf(v1.x, 0.f), fmaxf(v1.y, 0.f));
            } else if (EPI == 3) { // split-K atomic fp32
                float* c0 = (float*)C + (size_t)mA * Nc + col;
                float* c1 = (float*)C + (size_t)mB * Nc + col;
                atomicAdd(c0, v0.x); atomicAdd(c0 + 1, v0.y);
                atomicAdd(c1, v1.x); atomicAdd(c1 + 1, v1.y);
            } else {              // EPI 4: tf32-rounded fp32 (for attention)
                v0.x = to_tf32(v0.x); v0.y = to_tf32(v0.y);
                v1.x = to_tf32(v1.x); v1.y = to_tf32(v1.y);
                *(float2*)((float*)C + (size_t)mA * Nc + col) = v0;
                *(float2*)((float*)C + (size_t)mB * Nc + col) = v1;
            }
        }
    }
}

// ---------------- tensor-core flash attention (tf32 mma + ldmatrix) ---------
// Reads fp32 qkv (tf32-rounded by QKV GEMM); writes fp16 ctx.
#define KPITCH 68
#define VPITCH 72
#define PPITCH 68
#define KBUF (64 * KPITCH)
#define VBUF (64 * VPITCH)
#define ATT_SMEM ((2 * KBUF + 2 * VBUF + 64 * PPITCH) * 4)  // 89088 B

__global__ __launch_bounds__(128, 2)
void attention_mma_kernel(const float* __restrict__ QKV,
                          const float* __restrict__ tab,
                          __half* __restrict__ O) {
    extern __shared__ float smem[];
    const float* Vbp[2] = {smem + 2 * KBUF, smem + 2 * KBUF + VBUF};
    float* Ps = smem + 2 * KBUF + 2 * VBUF;

    const int bh = blockIdx.y;
    const int b = bh >> 4, h = bh & 15;
    const int q0 = blockIdx.x * 64;
    const int tid = threadIdx.x;
    const int wid = tid >> 5, lid = tid & 31;
    const int gid = lid >> 2, tig = lid & 3;
    const int lg = lid >> 3, r8 = lid & 7;
    const uint32_t smb = smem_u32(smem);

    const uint32_t kboff = ((uint32_t)((lg >> 1) * 8 + r8) * KPITCH + (lg & 1) * 4) * 4;
    const uint32_t paoff = smb
        + ((uint32_t)(wid * 16 + (lg & 1) * 8 + r8) * PPITCH + (lg >> 1) * 4) * 4
        + (uint32_t)(2 * KBUF + 2 * VBUF) * 4;

    uint32_t qfu[8][4];
    {
        const float* Qb = QKV + (size_t)(b * SEQ + q0 + wid * 16 + gid) * QKV_N + h * D_KV;
        #pragma unroll
        for (int k = 0; k < 8; k++) {
            qfu[k][0] = __float_as_uint(Qb[k * 8 + tig]);
            qfu[k][1] = __float_as_uint(Qb[8 * QKV_N + k * 8 + tig]);
            qfu[k][2] = __float_as_uint(Qb[k * 8 + tig + 4]);
            qfu[k][3] = __float_as_uint(Qb[8 * QKV_N + k * 8 + tig + 4]);
        }
    }

    auto load_kv = [&](int buf, int k0) {
        const float* Kg = QKV + INNER + h * D_KV;
        const float* Vg = QKV + 2 * INNER + h * D_KV;
        uint32_t kb = smb + (uint32_t)(buf * KBUF) * 4;
        uint32_t vb = smb + (uint32_t)(2 * KBUF + buf * VBUF) * 4;
        #pragma unroll
        for (int t = 0; t < 8; t++) {
            int idx = tid + t * 128;
            int row = idx >> 4;
            int c4 = (idx & 15) * 4;
            size_t gaddr = (size_t)(b * SEQ + k0 + row) * QKV_N + c4;
            CP_ASYNC16(kb + (uint32_t)(row * KPITCH + c4) * 4, Kg + gaddr);
            CP_ASYNC16(vb + (uint32_t)(row * VPITCH + c4) * 4, Vg + gaddr);
        }
    };

    float oacc[8][4];
    #pragma unroll
    for (int nj = 0; nj < 8; nj++)
        #pragma unroll
        for (int c = 0; c < 4; c++) oacc[nj][c] = 0.f;
    float m0 = -1e30f, m1 = -1e30f, l0 = 0.f, l1 = 0.f;

    load_kv(0, 0);
    CP_COMMIT();

    for (int it = 0; it < SEQ / 64; it++) {
        const int cur = it & 1;
        const int k0 = it * 64;
        cp_wait<0>();
        __syncthreads();
        if (it + 1 < SEQ / 64) {
            load_kv(cur ^ 1, k0 + 64);
            CP_COMMIT();
        }
        const uint32_t kbase = smb + (uint32_t)(cur * KBUF) * 4;
        const float* Vs = Vbp[cur];

        float sacc[8][4];
        #pragma unroll
        for (int nj = 0; nj < 8; nj++)
            #pragma unroll
            for (int c = 0; c < 4; c++) sacc[nj][c] = 0.f;
        #pragma unroll
        for (int ks = 0; ks < 8; ks++) {
            const uint32_t kso = (uint32_t)(ks * 8) * 4;
            uint32_t bb[4][4];
            #pragma unroll
            for (int p = 0; p < 4; p++)
                ldsm_x4(kbase + kboff + (uint32_t)(p * 16 * KPITCH) * 4 + kso, bb[p]);
            #pragma unroll
            for (int p = 0; p < 4; p++) {
                mma_tf32u(sacc[2 * p], qfu[ks], bb[p]);
                mma_tf32u(sacc[2 * p + 1], qfu[ks], bb[p] + 2);
            }
        }

        const float* bt = tab + h * TAB_LEN + 1023 + k0 - (q0 + wid * 16);
        float rx0 = -1e30f, rx1 = -1e30f;
        #pragma unroll
        for (int nj = 0; nj < 8; nj++) {
            int c = nj * 8 + 2 * tig;
            sacc[nj][0] += __ldg(bt + c - gid);
            sacc[nj][1] += __ldg(bt + c + 1 - gid);
            sacc[nj][2] += __ldg(bt + c - gid - 8);
            sacc[nj][3] += __ldg(bt + c + 1 - gid - 8);
            rx0 = fmaxf(rx0, fmaxf(sacc[nj][0], sacc[nj][1]));
            rx1 = fmaxf(rx1, fmaxf(sacc[nj][2], sacc[nj][3]));
        }
        rx0 = fmaxf(rx0, __shfl_xor_sync(0xFFFFFFFFu, rx0, 1));
        rx0 = fmaxf(rx0, __shfl_xor_sync(0xFFFFFFFFu, rx0, 2));
        rx1 = fmaxf(rx1, __shfl_xor_sync(0xFFFFFFFFu, rx1, 1));
        rx1 = fmaxf(rx1, __shfl_xor_sync(0xFFFFFFFFu, rx1, 2));
        float mn0 = fmaxf(m0, rx0), mn1 = fmaxf(m1, rx1);
        float sc0 = __expf(m0 - mn0), sc1 = __expf(m1 - mn1);
        m0 = mn0; m1 = mn1;

        float rs0 = 0.f, rs1 = 0.f;
        float* pw0 = Ps + (wid * 16 + gid) * PPITCH;
        float* pw1 = pw0 + 8 * PPITCH;
        #pragma unroll
        for (int nj = 0; nj < 8; nj++) {
            int c = nj * 8 + 2 * tig;
            float p0 = __expf(sacc[nj][0] - m0);
            float p1 = __expf(sacc[nj][1] - m0);
            float p2 = __expf(sacc[nj][2] - m1);
            float p3 = __expf(sacc[nj][3] - m1);
            rs0 += p0 + p1; rs1 += p2 + p3;
            *(float2*)(pw0 + c) = make_float2(to_tf32(p0), to_tf32(p1));
            *(float2*)(pw1 + c) = make_float2(to_tf32(p2), to_tf32(p3));
        }
        rs0 += __shfl_xor_sync(0xFFFFFFFFu, rs0, 1);
        rs0 += __shfl_xor_sync(0xFFFFFFFFu, rs0, 2);
        rs1 += __shfl_xor_sync(0xFFFFFFFFu, rs1, 1);
        rs1 += __shfl_xor_sync(0xFFFFFFFFu, rs1, 2);
        l0 = l0 * sc0 + rs0;
        l1 = l1 * sc1 + rs1;
        #pragma unroll
        for (int nj = 0; nj < 8; nj++) {
            oacc[nj][0] *= sc0; oacc[nj][1] *= sc0;
            oacc[nj][2] *= sc1; oacc[nj][3] *= sc1;
        }
        __syncwarp();

        #pragma unroll
        for (int k = 0; k < 8; k++) {
            uint32_t af[4];
            ldsm_x4(paoff + (uint32_t)(k * 8) * 4, af);
            #pragma unroll
            for (int nj = 0; nj < 8; nj++) {
                float bf[2];
                const float* vp = Vs + (k * 8 + tig) * VPITCH + nj * 8 + gid;
                bf[0] = vp[0];
                bf[1] = vp[4 * VPITCH];
                mma_tf32u(oacc[nj], af, (const uint32_t*)bf);
            }
        }
    }

    float i0 = 1.f / l0, i1 = 1.f / l1;
    __half* ob = O + (size_t)(b * SEQ + q0 + wid * 16 + gid) * INNER + h * D_KV;
    #pragma unroll
    for (int nj = 0; nj < 8; nj++) {
        int c = nj * 8 + 2 * tig;
        *(__half2*)(ob + c) = __floats2half2_rn(oacc[nj][0] * i0, oacc[nj][1] * i0);
        *(__half2*)(ob + 8 * INNER + c) =
            __floats2half2_rn(oacc[nj][2] * i1, oacc[nj][3] * i1);
    }
}

// ---------------- launch -----------------------------------------------------
extern "C" void kernel_launch(void* const* d_in, const int* in_sizes, int n_in,
                              void* d_out, int out_size) {
    const float* hidden  = (const float*)d_in[0];
    const float* ln1_w   = (const float*)d_in[1];
    const float* wq      = (const float*)d_in[2];
    const float* wk      = (const float*)d_in[3];
    const float* wv      = (const float*)d_in[4];
    const float* wo      = (const float*)d_in[5];
    const float* relbias = (const float*)d_in[6];
    const float* ln2_w   = (const float*)d_in[7];
    const float* wi      = (const float*)d_in[8];
    const float* wo_ff   = (const float*)d_in[9];
    float* out = (float*)d_out;

    __half *px, *pctx, *py, *pmid;
    float *pqkv, *ph, *pbias;
    __half *pwqkv, *pwo, *pwi, *pwoff;
    cudaGetSymbolAddress((void**)&px,    g_x);
    cudaGetSymbolAddress((void**)&pqkv,  g_qkv);
    cudaGetSymbolAddress((void**)&pctx,  g_ctx);
    cudaGetSymbolAddress((void**)&ph,    g_h);
    cudaGetSymbolAddress((void**)&py,    g_y);
    cudaGetSymbolAddress((void**)&pmid,  g_mid);
    cudaGetSymbolAddress((void**)&pbias, g_bias);
    cudaGetSymbolAddress((void**)&pwqkv, g_wqkv_h);
    cudaGetSymbolAddress((void**)&pwo,   g_wo_h);
    cudaGetSymbolAddress((void**)&pwi,   g_wi_h);
    cudaGetSymbolAddress((void**)&pwoff, g_woff_h);

    cudaFuncSetAttribute((gemm_f16_kernel<1, __half>), cudaFuncAttributeMaxDynamicSharedMemorySize, GEMM_SMEM);
    cudaFuncSetAttribute((gemm_f16_kernel<3, float>),  cudaFuncAttributeMaxDynamicSharedMemorySize, GEMM_SMEM);
    cudaFuncSetAttribute((gemm_f16_kernel<4, float>),  cudaFuncAttributeMaxDynamicSharedMemorySize, GEMM_SMEM);
    cudaFuncSetAttribute(attention_mma_kernel, cudaFuncAttributeMaxDynamicSharedMemorySize, ATT_SMEM);

    // 0: fused weight conversion to fp16
    convert_all_kernel<<<(N4TOT + 255) / 256, 256>>>(
        (const float4*)wq, (const float4*)wk, (const float4*)wv,
        (const float4*)wo, (const float4*)wi, (const float4*)wo_ff,
        pwqkv, pwo, pwi, pwoff);

    // 1,2
    bias_table_kernel<<<(TAB_LEN + 255) / 256, 256>>>(relbias, pbias);
    rmsnorm_kernel<<<M_ROWS, 256>>>(hidden, ln1_w, px);

    // 3: QKV projection, fp32 output rounded to tf32 (feeds tf32 attention)
    gemm_f16_kernel<4, float><<<dim3(QKV_N / 128, M_ROWS / 128), 256, GEMM_SMEM>>>(
        px, pwqkv, pqkv, M_ROWS, QKV_N, D_MODEL, D_MODEL);

    // 4: attention (fp32 in, fp16 ctx out)
    attention_mma_kernel<<<dim3(SEQ / 64, BATCH * N_HEADS), 128, ATT_SMEM>>>(
        pqkv, pbias, pctx);

    // 5 (ncu target): h = hidden + ctx @ wo^T (split-K2 atomic)
    cudaMemcpyAsync(ph, hidden, (size_t)M_ROWS * D_MODEL * sizeof(float),
                    cudaMemcpyDeviceToDevice);
    gemm_f16_kernel<3, float><<<dim3(D_MODEL / 128, M_ROWS / 128, 2), 256, GEMM_SMEM>>>(
        pctx, pwo, ph, M_ROWS, D_MODEL, INNER, INNER / 2);

    // 6
    rmsnorm_kernel<<<M_ROWS, 256>>>(ph, ln2_w, py);

    // 7: mid = relu(y @ wi^T) -> fp16
    gemm_f16_kernel<1, __half><<<dim3(D_FF / 128, M_ROWS / 128), 256, GEMM_SMEM>>>(
        py, pwi, pmid, M_ROWS, D_FF, D_MODEL, D_MODEL);

    // 8: out = h + mid @ wo_ff^T (split-K2 atomic)
    cudaMemcpyAsync(out, ph, (size_t)M_ROWS * D_MODEL * sizeof(float),
                    cudaMemcpyDeviceToDevice);
    gemm_f16_kernel<3, float><<<dim3(D_MODEL / 128, M_ROWS / 128, 2), 256, GEMM_SMEM>>>(
        pmid, pwoff, out, M_ROWS, D_MODEL, D_FF, D_FF / 2);
}

// round 15
// speedup vs baseline: 1.6278x; 1.1576x over previous
#include <cuda_runtime.h>
#include <cuda_fp16.h>
#include <math.h>
#include <stdint.h>

#define D_MODEL 1024
#define N_HEADS 16
#define D_KV    64
#define INNER   1024
#define QKV_N   3072
#define D_FF    4096
#define SEQ     1024
#define BATCH   2
#define M_ROWS  (BATCH * SEQ)   // 2048
#define TAB_LEN 2047            // rel in [-1023, 1023]

// ---------------- scratch (device globals: no allocation allowed) ----------
__device__ __half g_x   [M_ROWS * D_MODEL];
__device__ __half g_qkv [M_ROWS * QKV_N];
__device__ __half g_ctx [M_ROWS * INNER];
__device__ float  g_h   [M_ROWS * D_MODEL];
__device__ __half g_y   [M_ROWS * D_MODEL];
__device__ __half g_mid [M_ROWS * D_FF];
__device__ float  g_bias[N_HEADS * TAB_LEN];
// fp16 weights (wq/wk/wv packed)
__device__ __half g_wqkv_h[QKV_N * D_MODEL];
__device__ __half g_wo_h  [D_MODEL * INNER];
__device__ __half g_wi_h  [D_FF * D_MODEL];
__device__ __half g_woff_h[D_MODEL * D_FF];

// ---------------- helpers ----------------------------------------------------
__device__ __forceinline__ uint32_t smem_u32(const void* p) {
    uint32_t a;
    asm("{ .reg .u64 t; cvta.to.shared.u64 t, %1; cvt.u32.u64 %0, t; }"
        : "=r"(a) : "l"(p));
    return a;
}
#define CP_ASYNC16(sm, gp) \
    asm volatile("cp.async.cg.shared.global [%0], [%1], 16;" :: "r"(sm), "l"(gp))
#define CP_COMMIT() asm volatile("cp.async.commit_group;" ::: "memory")
template <int NN>
__device__ __forceinline__ void cp_wait() {
    asm volatile("cp.async.wait_group %0;" :: "n"(NN) : "memory");
}

// fp16 mma: m16n8k16, fp32 accumulate
__device__ __forceinline__ void mma_f16(float* d, const uint32_t* a, const uint32_t* b) {
    asm volatile(
        "mma.sync.aligned.m16n8k16.row.col.f32.f16.f16.f32 "
        "{%0,%1,%2,%3}, {%4,%5,%6,%7}, {%8,%9}, {%0,%1,%2,%3};"
        : "+f"(d[0]), "+f"(d[1]), "+f"(d[2]), "+f"(d[3])
        : "r"(a[0]), "r"(a[1]), "r"(a[2]), "r"(a[3]), "r"(b[0]), "r"(b[1]));
}
__device__ __forceinline__ void ldsm_x4(uint32_t addr, uint32_t* r) {
    asm volatile("ldmatrix.sync.aligned.m8n8.x4.shared.b16 {%0,%1,%2,%3}, [%4];"
        : "=r"(r[0]), "=r"(r[1]), "=r"(r[2]), "=r"(r[3]) : "r"(addr));
}
__device__ __forceinline__ void ldsm_x4_t(uint32_t addr, uint32_t* r) {
    asm volatile("ldmatrix.sync.aligned.m8n8.x4.trans.shared.b16 {%0,%1,%2,%3}, [%4];"
        : "=r"(r[0]), "=r"(r[1]), "=r"(r[2]), "=r"(r[3]) : "r"(addr));
}

// ---------------- fused weight conversion to fp16 (one launch) --------------
#define N4S ((INNER * D_MODEL) / 4)
#define N4B ((D_FF * D_MODEL) / 4)
#define N4TOT (4 * N4S + 2 * N4B)
__global__ void convert_all_kernel(const float4* __restrict__ wq,
                                   const float4* __restrict__ wk,
                                   const float4* __restrict__ wv,
                                   const float4* __restrict__ wo,
                                   const float4* __restrict__ wi,
                                   const float4* __restrict__ woff,
                                   __half* __restrict__ dqkv,
                                   __half* __restrict__ dwo,
                                   __half* __restrict__ dwi,
                                   __half* __restrict__ dwoff) {
    int i = blockIdx.x * blockDim.x + threadIdx.x;
    if (i >= N4TOT) return;
    const float4* src;
    __half* dst;
    int off;
    if (i < 3 * N4S)      { int s = i / N4S; off = i - s * N4S;
                            src = (s == 0) ? wq : (s == 1) ? wk : wv;
                            dst = dqkv + (size_t)s * (INNER * D_MODEL); }
    else if (i < 4 * N4S) { off = i - 3 * N4S; src = wo;   dst = dwo; }
    else if (i < 4 * N4S + N4B) { off = i - 4 * N4S; src = wi; dst = dwi; }
    else                  { off = i - 4 * N4S - N4B; src = woff; dst = dwoff; }
    float4 v = src[off];
    __half2* d2 = (__half2*)(dst) + off * 2;
    d2[0] = __floats2half2_rn(v.x, v.y);
    d2[1] = __floats2half2_rn(v.z, v.w);
}

// ---------------- RMSNorm (T5), output fp16 ----------------------------------
__global__ void rmsnorm_kernel(const float* __restrict__ in,
                               const float* __restrict__ w,
                               __half* __restrict__ out) {
    int row = blockIdx.x;
    const float4* inr = (const float4*)(in + (size_t)row * D_MODEL);
    float4 v = inr[threadIdx.x];
    float ss = v.x * v.x + v.y * v.y + v.z * v.z + v.w * v.w;
    #pragma unroll
    for (int o = 16; o; o >>= 1) ss += __shfl_xor_sync(0xFFFFFFFFu, ss, o);
    __shared__ float sred[8];
    if ((threadIdx.x & 31) == 0) sred[threadIdx.x >> 5] = ss;
    __syncthreads();
    float total = 0.f;
    #pragma unroll
    for (int i = 0; i < 8; i++) total += sred[i];
    float scale = rsqrtf(total * (1.0f / D_MODEL) + 1e-6f);
    float4 wv = ((const float4*)w)[threadIdx.x];
    __half2* o2 = (__half2*)(out + (size_t)row * D_MODEL) + threadIdx.x * 2;
    o2[0] = __floats2half2_rn(v.x * scale * wv.x, v.y * scale * wv.y);
    o2[1] = __floats2half2_rn(v.z * scale * wv.z, v.w * scale * wv.w);
}

// ---------------- relative position bias table ------------------------------
__global__ void bias_table_kernel(const float* __restrict__ rel_bias,
                                  float* __restrict__ tab) {
    int i = blockIdx.x * blockDim.x + threadIdx.x;
    if (i >= TAB_LEN) return;
    int rel = i - 1023;
    int rb = (rel > 0) ? 16 : 0;
    int rp = rel < 0 ? -rel : rel;
    int val;
    if (rp < 8) {
        val = rp;
    } else {
        float t = logf((float)rp * 0.125f) * (8.0f / 2.772588722239781f);
        int large = 8 + (int)t;
        val = large < 15 ? large : 15;
    }
    int bucket = rb + val;
    #pragma unroll
    for (int h = 0; h < N_HEADS; h++)
        tab[h * TAB_LEN + i] = rel_bias[bucket * N_HEADS + h];
}

// ---------------- fp16 mma GEMM: 8 warps x 64x32 tiles, 3-stage cp.async ----
// C[M,N] = A[M,K] @ W[N,K]^T. A,W fp16. Accumulate fp32.
// EPI: 1 = relu -> fp16, 3 = atomicAdd fp32 (split-K), 5 = plain fp16.
#define HPITCH 40
#define TILEH  (128 * HPITCH)
#define BUFFH  (2 * TILEH)
#define GEMM_SMEM (3 * BUFFH * 2)      // 61440 bytes

template <int EPI, typename CT>
__global__ __launch_bounds__(256, 2)
void gemm_f16_kernel(const __half* __restrict__ A, const __half* __restrict__ W,
                     CT* __restrict__ C, int M, int Nc, int Kstride, int Klen) {
    extern __shared__ __half smh[];
    const int tid = threadIdx.x;
    const int wid = tid >> 5, lid = tid & 31;
    const int gid = lid >> 2, tig = lid & 3;
    const int wm = wid >> 2, wn = wid & 3;
    const int m0 = blockIdx.y * 128;
    const int n0 = blockIdx.x * 128;
    const int kbase = blockIdx.z * Klen;
    const int T = Klen >> 5;

    float acc[4][4][4];
    #pragma unroll
    for (int i = 0; i < 4; i++)
        #pragma unroll
        for (int j = 0; j < 4; j++)
            #pragma unroll
            for (int c = 0; c < 4; c++) acc[i][j][c] = 0.f;

    const uint32_t smb = smem_u32(smh);
    const int lg = lid >> 3, r8 = lid & 7;
    const uint32_t aoff = ((uint32_t)(wm * 64 + (lg & 1) * 8 + r8) * HPITCH
                           + (lg >> 1) * 8) * 2;
    const uint32_t boff = ((uint32_t)(wn * 32 + (lg >> 1) * 8 + r8) * HPITCH
                           + (lg & 1) * 8) * 2 + (uint32_t)TILEH * 2;

    auto load_tiles = [&](int buf, int k0) {
        uint32_t base = smb + (uint32_t)buf * (BUFFH * 2);
        #pragma unroll
        for (int t = 0; t < 2; t++) {
            int c = tid + t * 256;
            int row = c >> 2;
            int ch = (c & 3) * 8;
            uint32_t soff = (uint32_t)row * (HPITCH * 2) + ch * 2;
            CP_ASYNC16(base + soff,
                       A + (size_t)(m0 + row) * Kstride + kbase + k0 + ch);
            CP_ASYNC16(base + (uint32_t)TILEH * 2 + soff,
                       W + (size_t)(n0 + row) * Kstride + kbase + k0 + ch);
        }
    };

    load_tiles(0, 0);
    CP_COMMIT();
    load_tiles(1, 32);
    CP_COMMIT();

    int stage = 0;
    for (int i = 0; i < T; i++) {
        if (i < T - 1) cp_wait<1>(); else cp_wait<0>();
        __syncthreads();
        if (i + 2 < T) {
            int nst = stage + 2; if (nst >= 3) nst -= 3;
            load_tiles(nst, (i + 2) << 5);
            CP_COMMIT();
        }

        const uint32_t base = smb + (uint32_t)stage * (BUFFH * 2);
        #pragma unroll
        for (int kh = 0; kh < 2; kh++) {
            const uint32_t kso = (uint32_t)kh * 32;
            uint32_t a[4][4], bb[2][4];
            #pragma unroll
            for (int mi = 0; mi < 4; mi++)
                ldsm_x4(base + aoff + (uint32_t)(mi * 16 * HPITCH) * 2 + kso, a[mi]);
            #pragma unroll
            for (int p = 0; p < 2; p++)
                ldsm_x4(base + boff + (uint32_t)(p * 16 * HPITCH) * 2 + kso, bb[p]);
            #pragma unroll
            for (int mi = 0; mi < 4; mi++) {
                mma_f16(acc[mi][0], a[mi], bb[0]);
                mma_f16(acc[mi][1], a[mi], bb[0] + 2);
                mma_f16(acc[mi][2], a[mi], bb[1]);
                mma_f16(acc[mi][3], a[mi], bb[1] + 2);
            }
        }
        stage = (stage + 1 == 3) ? 0 : stage + 1;
    }

    #pragma unroll
    for (int mi = 0; mi < 4; mi++) {
        const int mA = m0 + wm * 64 + mi * 16 + gid;
        const int mB = mA + 8;
        #pragma unroll
        for (int nj = 0; nj < 4; nj++) {
            const int col = n0 + wn * 32 + nj * 8 + tig * 2;
            float2 v0 = make_float2(acc[mi][nj][0], acc[mi][nj][1]);
            float2 v1 = make_float2(acc[mi][nj][2], acc[mi][nj][3]);
            if (EPI == 1 || EPI == 5) {
                if (EPI == 1) {
                    v0.x = fmaxf(v0.x, 0.f); v0.y = fmaxf(v0.y, 0.f);
                    v1.x = fmaxf(v1.x, 0.f); v1.y = fmaxf(v1.y, 0.f);
                }
                *(__half2*)((__half*)C + (size_t)mA * Nc + col) =
                    __floats2half2_rn(v0.x, v0.y);
                *(__half2*)((__half*)C + (size_t)mB * Nc + col) =
                    __floats2half2_rn(v1.x, v1.y);
            } else {  // EPI == 3
                float* c0 = (float*)C + (size_t)mA * Nc + col;
                float* c1 = (float*)C + (size_t)mB * Nc + col;
                atomicAdd(c0, v0.x); atomicAdd(c0 + 1, v0.y);
                atomicAdd(c1, v1.x); atomicAdd(c1 + 1, v1.y);
            }
        }
    }
}

// ---------------- fp16 tensor-core flash attention ---------------------------
// All pitches 72 halves (144 B) -> bank 4*row, conflict-free ldmatrix/stores.
#define AQP 72
#define QBUF  (64 * AQP)
#define KBUFH (64 * AQP)
#define VBUFH (64 * AQP)
#define PBUF  (64 * AQP)
#define KOFF(b)  (QBUF + (b) * KBUFH)
#define VOFF(b)  (QBUF + 2 * KBUFH + (b) * VBUFH)
#define POFF     (QBUF + 2 * KBUFH + 2 * VBUFH)
#define ATT_SMEM ((QBUF + 2 * KBUFH + 2 * VBUFH + PBUF) * 2)  // 55296 B

__global__ __launch_bounds__(128, 2)
void attention_f16_kernel(const __half* __restrict__ QKV,
                          const float* __restrict__ tab,
                          __half* __restrict__ O) {
    extern __shared__ __half smha[];
    const int bh = blockIdx.y;
    const int b = bh >> 4, h = bh & 15;
    const int q0 = blockIdx.x * 64;
    const int tid = threadIdx.x;
    const int wid = tid >> 5, lid = tid & 31;
    const int gid = lid >> 2, tig = lid & 3;
    const int lg = lid >> 3, r8 = lid & 7;
    const uint32_t smb = smem_u32(smha);

    // ldmatrix lane addresses (bytes)
    // Q A-frag (non-trans): tiles (m0-7,klo),(m8-15,klo),(m0-7,khi),(m8-15,khi)
    const uint32_t qa = smb + ((uint32_t)(wid * 16 + (lg & 1) * 8 + r8) * AQP
                               + (lg >> 1) * 8) * 2;
    // K B-frag (non-trans): tiles (n0-7,klo),(n0-7,khi),(n8-15,klo),(n8-15,khi)
    const uint32_t ka = ((uint32_t)((lg >> 1) * 8 + r8) * AQP + (lg & 1) * 8) * 2;
    // V B-frag (trans): tiles (klo,nlo),(khi,nlo),(klo,nhi),(khi,nhi)
    const uint32_t va = ((uint32_t)((lg & 1) * 8 + r8) * AQP + (lg >> 1) * 8) * 2;
    // P A-frag (non-trans)
    const uint32_t pa = smb + ((uint32_t)POFF + (uint32_t)(wid * 16 + (lg & 1) * 8 + r8) * AQP
                               + (lg >> 1) * 8) * 2;

    auto load_q = [&]() {
        #pragma unroll
        for (int t = 0; t < 4; t++) {
            int c = tid + t * 128;              // 0..511
            int row = c >> 3, ch = (c & 7) * 8;
            CP_ASYNC16(smb + ((uint32_t)row * AQP + ch) * 2,
                       QKV + (size_t)(b * SEQ + q0 + row) * QKV_N + h * D_KV + ch);
        }
    };
    auto load_kv = [&](int buf, int k0) {
        #pragma unroll
        for (int t = 0; t < 4; t++) {
            int c = tid + t * 128;
            int row = c >> 3, ch = (c & 7) * 8;
            size_t g = (size_t)(b * SEQ + k0 + row) * QKV_N + h * D_KV + ch;
            CP_ASYNC16(smb + ((uint32_t)KOFF(buf) + (uint32_t)row * AQP + ch) * 2,
                       QKV + INNER + g);
            CP_ASYNC16(smb + ((uint32_t)VOFF(buf) + (uint32_t)row * AQP + ch) * 2,
                       QKV + 2 * INNER + g);
        }
    };

    float oacc[8][4];
    #pragma unroll
    for (int nj = 0; nj < 8; nj++)
        #pragma unroll
        for (int c = 0; c < 4; c++) oacc[nj][c] = 0.f;
    float m0 = -1e30f, m1 = -1e30f, l0 = 0.f, l1 = 0.f;
    uint32_t qf[4][4];

    load_q();
    load_kv(0, 0);
    CP_COMMIT();

    for (int it = 0; it < SEQ / 64; it++) {
        const int cur = it & 1;
        const int k0 = it * 64;
        cp_wait<0>();
        __syncthreads();
        if (it + 1 < SEQ / 64) {
            load_kv(cur ^ 1, k0 + 64);
            CP_COMMIT();
        }
        if (it == 0) {
            #pragma unroll
            for (int ks = 0; ks < 4; ks++)
                ldsm_x4(qa + (uint32_t)ks * 32, qf[ks]);
        }
        const uint32_t kb = smb + (uint32_t)KOFF(cur) * 2 + ka;
        const uint32_t vb = smb + (uint32_t)VOFF(cur) * 2 + va;

        // S = Q @ K^T
        float sacc[8][4];
        #pragma unroll
        for (int nj = 0; nj < 8; nj++)
            #pragma unroll
            for (int c = 0; c < 4; c++) sacc[nj][c] = 0.f;
        #pragma unroll
        for (int ks = 0; ks < 4; ks++) {
            const uint32_t kso = (uint32_t)ks * 32;
            #pragma unroll
            for (int p = 0; p < 4; p++) {
                uint32_t bb[4];
                ldsm_x4(kb + (uint32_t)(p * 16 * AQP) * 2 + kso, bb);
                mma_f16(sacc[2 * p], qf[ks], bb);
                mma_f16(sacc[2 * p + 1], qf[ks], bb + 2);
            }
        }

        // bias + online softmax (rows gid / gid+8)
        const float* bt = tab + h * TAB_LEN + 1023 + k0 - (q0 + wid * 16);
        float rx0 = -1e30f, rx1 = -1e30f;
        #pragma unroll
        for (int nj = 0; nj < 8; nj++) {
            int c = nj * 8 + 2 * tig;
            sacc[nj][0] += __ldg(bt + c - gid);
            sacc[nj][1] += __ldg(bt + c + 1 - gid);
            sacc[nj][2] += __ldg(bt + c - gid - 8);
            sacc[nj][3] += __ldg(bt + c + 1 - gid - 8);
            rx0 = fmaxf(rx0, fmaxf(sacc[nj][0], sacc[nj][1]));
            rx1 = fmaxf(rx1, fmaxf(sacc[nj][2], sacc[nj][3]));
        }
        rx0 = fmaxf(rx0, __shfl_xor_sync(0xFFFFFFFFu, rx0, 1));
        rx0 = fmaxf(rx0, __shfl_xor_sync(0xFFFFFFFFu, rx0, 2));
        rx1 = fmaxf(rx1, __shfl_xor_sync(0xFFFFFFFFu, rx1, 1));
        rx1 = fmaxf(rx1, __shfl_xor_sync(0xFFFFFFFFu, rx1, 2));
        float mn0 = fmaxf(m0, rx0), mn1 = fmaxf(m1, rx1);
        float sc0 = __expf(m0 - mn0), sc1 = __expf(m1 - mn1);
        m0 = mn0; m1 = mn1;

        float rs0 = 0.f, rs1 = 0.f;
        __half* pr0 = smha + POFF + (wid * 16 + gid) * AQP;
        __half* pr1 = pr0 + 8 * AQP;
        #pragma unroll
        for (int nj = 0; nj < 8; nj++) {
            int c = nj * 8 + 2 * tig;
            float p0 = __expf(sacc[nj][0] - m0);
            float p1 = __expf(sacc[nj][1] - m0);
            float p2 = __expf(sacc[nj][2] - m1);
            float p3 = __expf(sacc[nj][3] - m1);
            rs0 += p0 + p1; rs1 += p2 + p3;
            *(__half2*)(pr0 + c) = __floats2half2_rn(p0, p1);
            *(__half2*)(pr1 + c) = __floats2half2_rn(p2, p3);
        }
        rs0 += __shfl_xor_sync(0xFFFFFFFFu, rs0, 1);
        rs0 += __shfl_xor_sync(0xFFFFFFFFu, rs0, 2);
        rs1 += __shfl_xor_sync(0xFFFFFFFFu, rs1, 1);
        rs1 += __shfl_xor_sync(0xFFFFFFFFu, rs1, 2);
        l0 = l0 * sc0 + rs0;
        l1 = l1 * sc1 + rs1;
        #pragma unroll
        for (int nj = 0; nj < 8; nj++) {
            oacc[nj][0] *= sc0; oacc[nj][1] *= sc0;
            oacc[nj][2] *= sc1; oacc[nj][3] *= sc1;
        }
        __syncwarp();

        // O += P @ V (P non-trans A-frags, V trans B-frags)
        #pragma unroll
        for (int ks = 0; ks < 4; ks++) {
            uint32_t af[4];
            ldsm_x4(pa + (uint32_t)ks * 32, af);
            #pragma unroll
            for (int p = 0; p < 4; p++) {
                uint32_t bb[4];
                ldsm_x4_t(vb + (uint32_t)(ks * 16 * AQP) * 2 + (uint32_t)p * 32, bb);
                mma_f16(oacc[2 * p], af, bb);
                mma_f16(oacc[2 * p + 1], af, bb + 2);
            }
        }
    }

    float i0 = 1.f / l0, i1 = 1.f / l1;
    __half* ob = O + (size_t)(b * SEQ + q0 + wid * 16 + gid) * INNER + h * D_KV;
    #pragma unroll
    for (int nj = 0; nj < 8; nj++) {
        int c = nj * 8 + 2 * tig;
        *(__half2*)(ob + c) = __floats2half2_rn(oacc[nj][0] * i0, oacc[nj][1] * i0);
        *(__half2*)(ob + 8 * INNER + c) =
            __floats2half2_rn(oacc[nj][2] * i1, oacc[nj][3] * i1);
    }
}

// ---------------- launch -----------------------------------------------------
extern "C" void kernel_launch(void* const* d_in, const int* in_sizes, int n_in,
                              void* d_out, int out_size) {
    const float* hidden  = (const float*)d_in[0];
    const float* ln1_w   = (const float*)d_in[1];
    const float* wq      = (const float*)d_in[2];
    const float* wk      = (const float*)d_in[3];
    const float* wv      = (const float*)d_in[4];
    const float* wo      = (const float*)d_in[5];
    const float* relbias = (const float*)d_in[6];
    const float* ln2_w   = (const float*)d_in[7];
    const float* wi      = (const float*)d_in[8];
    const float* wo_ff   = (const float*)d_in[9];
    float* out = (float*)d_out;

    __half *px, *pqkv, *pctx, *py, *pmid;
    float *ph, *pbias;
    __half *pwqkv, *pwo, *pwi, *pwoff;
    cudaGetSymbolAddress((void**)&px,    g_x);
    cudaGetSymbolAddress((void**)&pqkv,  g_qkv);
    cudaGetSymbolAddress((void**)&pctx,  g_ctx);
    cudaGetSymbolAddress((void**)&ph,    g_h);
    cudaGetSymbolAddress((void**)&py,    g_y);
    cudaGetSymbolAddress((void**)&pmid,  g_mid);
    cudaGetSymbolAddress((void**)&pbias, g_bias);
    cudaGetSymbolAddress((void**)&pwqkv, g_wqkv_h);
    cudaGetSymbolAddress((void**)&pwo,   g_wo_h);
    cudaGetSymbolAddress((void**)&pwi,   g_wi_h);
    cudaGetSymbolAddress((void**)&pwoff, g_woff_h);

    cudaFuncSetAttribute((gemm_f16_kernel<1, __half>), cudaFuncAttributeMaxDynamicSharedMemorySize, GEMM_SMEM);
    cudaFuncSetAttribute((gemm_f16_kernel<3, float>),  cudaFuncAttributeMaxDynamicSharedMemorySize, GEMM_SMEM);
    cudaFuncSetAttribute((gemm_f16_kernel<5, __half>), cudaFuncAttributeMaxDynamicSharedMemorySize, GEMM_SMEM);
    cudaFuncSetAttribute(attention_f16_kernel, cudaFuncAttributeMaxDynamicSharedMemorySize, ATT_SMEM);

    // 0: fused weight conversion to fp16
    convert_all_kernel<<<(N4TOT + 255) / 256, 256>>>(
        (const float4*)wq, (const float4*)wk, (const float4*)wv,
        (const float4*)wo, (const float4*)wi, (const float4*)wo_ff,
        pwqkv, pwo, pwi, pwoff);

    // 1,2
    bias_table_kernel<<<(TAB_LEN + 255) / 256, 256>>>(relbias, pbias);
    rmsnorm_kernel<<<M_ROWS, 256>>>(hidden, ln1_w, px);

    // 3: QKV projection -> fp16 qkv
    gemm_f16_kernel<5, __half><<<dim3(QKV_N / 128, M_ROWS / 128), 256, GEMM_SMEM>>>(
        px, pwqkv, pqkv, M_ROWS, QKV_N, D_MODEL, D_MODEL);

    // 4: fp16 attention -> fp16 ctx
    attention_f16_kernel<<<dim3(SEQ / 64, BATCH * N_HEADS), 128, ATT_SMEM>>>(
        pqkv, pbias, pctx);

    // 5: h = hidden + ctx @ wo^T (split-K2 atomic)
    cudaMemcpyAsync(ph, hidden, (size_t)M_ROWS * D_MODEL * sizeof(float),
                    cudaMemcpyDeviceToDevice);
    gemm_f16_kernel<3, float><<<dim3(D_MODEL / 128, M_ROWS / 128, 2), 256, GEMM_SMEM>>>(
        pctx, pwo, ph, M_ROWS, D_MODEL, INNER, INNER / 2);

    // 6
    rmsnorm_kernel<<<M_ROWS, 256>>>(ph, ln2_w, py);

    // 7: mid = relu(y @ wi^T) -> fp16
    gemm_f16_kernel<1, __half><<<dim3(D_FF / 128, M_ROWS / 128), 256, GEMM_SMEM>>>(
        py, pwi, pmid, M_ROWS, D_FF, D_MODEL, D_MODEL);

    // 8: out = h + mid @ wo_ff^T (split-K2 atomic)
    cudaMemcpyAsync(out, ph, (size_t)M_ROWS * D_MODEL * sizeof(float),
                    cudaMemcpyDeviceToDevice);
    gemm_f16_kernel<3, float><<<dim3(D_MODEL / 128, M_ROWS / 128, 2), 256, GEMM_SMEM>>>(
        pmid, pwoff, out, M_ROWS, D_MODEL, D_FF, D_FF / 2);
}

// round 17
// speedup vs baseline: 1.6613x; 1.0206x over previous
#include <cuda_runtime.h>
#include <cuda_fp16.h>
#include <math.h>
#include <stdint.h>

#define D_MODEL 1024
#define N_HEADS 16
#define D_KV    64
#define INNER   1024
#define QKV_N   3072
#define D_FF    4096
#define SEQ     1024
#define BATCH   2
#define M_ROWS  (BATCH * SEQ)   // 2048
#define TAB_LEN 2047            // rel in [-1023, 1023]

// ---------------- scratch (device globals: no allocation allowed) ----------
__device__ __half g_x   [M_ROWS * D_MODEL];
__device__ __half g_qkv [M_ROWS * QKV_N];
__device__ __half g_ctx [M_ROWS * INNER];
__device__ float  g_h   [M_ROWS * D_MODEL];
__device__ __half g_y   [M_ROWS * D_MODEL];
__device__ __half g_mid [M_ROWS * D_FF];
__device__ float  g_bias[N_HEADS * TAB_LEN];
// fp16 weights (wq/wk/wv packed)
__device__ __half g_wqkv_h[QKV_N * D_MODEL];
__device__ __half g_wo_h  [D_MODEL * INNER];
__device__ __half g_wi_h  [D_FF * D_MODEL];
__device__ __half g_woff_h[D_MODEL * D_FF];

// ---------------- helpers ----------------------------------------------------
__device__ __forceinline__ uint32_t smem_u32(const void* p) {
    uint32_t a;
    asm("{ .reg .u64 t; cvta.to.shared.u64 t, %1; cvt.u32.u64 %0, t; }"
        : "=r"(a) : "l"(p));
    return a;
}
#define CP_ASYNC16(sm, gp) \
    asm volatile("cp.async.cg.shared.global [%0], [%1], 16;" :: "r"(sm), "l"(gp))
#define CP_COMMIT() asm volatile("cp.async.commit_group;" ::: "memory")
template <int NN>
__device__ __forceinline__ void cp_wait() {
    asm volatile("cp.async.wait_group %0;" :: "n"(NN) : "memory");
}

// fp16 mma: m16n8k16, fp32 accumulate
__device__ __forceinline__ void mma_f16(float* d, const uint32_t* a, const uint32_t* b) {
    asm volatile(
        "mma.sync.aligned.m16n8k16.row.col.f32.f16.f16.f32 "
        "{%0,%1,%2,%3}, {%4,%5,%6,%7}, {%8,%9}, {%0,%1,%2,%3};"
        : "+f"(d[0]), "+f"(d[1]), "+f"(d[2]), "+f"(d[3])
        : "r"(a[0]), "r"(a[1]), "r"(a[2]), "r"(a[3]), "r"(b[0]), "r"(b[1]));
}
__device__ __forceinline__ void ldsm_x4(uint32_t addr, uint32_t* r) {
    asm volatile("ldmatrix.sync.aligned.m8n8.x4.shared.b16 {%0,%1,%2,%3}, [%4];"
        : "=r"(r[0]), "=r"(r[1]), "=r"(r[2]), "=r"(r[3]) : "r"(addr));
}
__device__ __forceinline__ void ldsm_x4_t(uint32_t addr, uint32_t* r) {
    asm volatile("ldmatrix.sync.aligned.m8n8.x4.trans.shared.b16 {%0,%1,%2,%3}, [%4];"
        : "=r"(r[0]), "=r"(r[1]), "=r"(r[2]), "=r"(r[3]) : "r"(addr));
}

// ---------------- fused weight conversion to fp16 (one launch) --------------
#define N4S ((INNER * D_MODEL) / 4)
#define N4B ((D_FF * D_MODEL) / 4)
#define N4TOT (4 * N4S + 2 * N4B)
__global__ void convert_all_kernel(const float4* __restrict__ wq,
                                   const float4* __restrict__ wk,
                                   const float4* __restrict__ wv,
                                   const float4* __restrict__ wo,
                                   const float4* __restrict__ wi,
                                   const float4* __restrict__ woff,
                                   __half* __restrict__ dqkv,
                                   __half* __restrict__ dwo,
                                   __half* __restrict__ dwi,
                                   __half* __restrict__ dwoff) {
    int i = blockIdx.x * blockDim.x + threadIdx.x;
    if (i >= N4TOT) return;
    const float4* src;
    __half* dst;
    int off;
    if (i < 3 * N4S)      { int s = i / N4S; off = i - s * N4S;
                            src = (s == 0) ? wq : (s == 1) ? wk : wv;
                            dst = dqkv + (size_t)s * (INNER * D_MODEL); }
    else if (i < 4 * N4S) { off = i - 3 * N4S; src = wo;   dst = dwo; }
    else if (i < 4 * N4S + N4B) { off = i - 4 * N4S; src = wi; dst = dwi; }
    else                  { off = i - 4 * N4S - N4B; src = woff; dst = dwoff; }
    float4 v = src[off];
    __half2* d2 = (__half2*)(dst) + off * 2;
    d2[0] = __floats2half2_rn(v.x, v.y);
    d2[1] = __floats2half2_rn(v.z, v.w);
}

// ---------------- RMSNorm (T5), output fp16 ----------------------------------
__global__ void rmsnorm_kernel(const float* __restrict__ in,
                               const float* __restrict__ w,
                               __half* __restrict__ out) {
    int row = blockIdx.x;
    const float4* inr = (const float4*)(in + (size_t)row * D_MODEL);
    float4 v = inr[threadIdx.x];
    float ss = v.x * v.x + v.y * v.y + v.z * v.z + v.w * v.w;
    #pragma unroll
    for (int o = 16; o; o >>= 1) ss += __shfl_xor_sync(0xFFFFFFFFu, ss, o);
    __shared__ float sred[8];
    if ((threadIdx.x & 31) == 0) sred[threadIdx.x >> 5] = ss;
    __syncthreads();
    float total = 0.f;
    #pragma unroll
    for (int i = 0; i < 8; i++) total += sred[i];
    float scale = rsqrtf(total * (1.0f / D_MODEL) + 1e-6f);
    float4 wv = ((const float4*)w)[threadIdx.x];
    __half2* o2 = (__half2*)(out + (size_t)row * D_MODEL) + threadIdx.x * 2;
    o2[0] = __floats2half2_rn(v.x * scale * wv.x, v.y * scale * wv.y);
    o2[1] = __floats2half2_rn(v.z * scale * wv.z, v.w * scale * wv.w);
}

// ---------------- relative position bias table ------------------------------
__global__ void bias_table_kernel(const float* __restrict__ rel_bias,
                                  float* __restrict__ tab) {
    int i = blockIdx.x * blockDim.x + threadIdx.x;
    if (i >= TAB_LEN) return;
    int rel = i - 1023;
    int rb = (rel > 0) ? 16 : 0;
    int rp = rel < 0 ? -rel : rel;
    int val;
    if (rp < 8) {
        val = rp;
    } else {
        float t = logf((float)rp * 0.125f) * (8.0f / 2.772588722239781f);
        int large = 8 + (int)t;
        val = large < 15 ? large : 15;
    }
    int bucket = rb + val;
    #pragma unroll
    for (int h = 0; h < N_HEADS; h++)
        tab[h * TAB_LEN + i] = rel_bias[bucket * N_HEADS + h];
}

// ---------------- fp16 mma GEMM: 8 warps x 64x32 tiles, 3-stage cp.async ----
// EPI: 1 = relu -> fp16, 3 = atomicAdd fp32 (split-K), 5 = plain fp16.
#define HPITCH 40
#define TILEH  (128 * HPITCH)
#define BUFFH  (2 * TILEH)
#define GEMM_SMEM (3 * BUFFH * 2)      // 61440 bytes

template <int EPI, typename CT>
__global__ __launch_bounds__(256, 2)
void gemm_f16_kernel(const __half* __restrict__ A, const __half* __restrict__ W,
                     CT* __restrict__ C, int M, int Nc, int Kstride, int Klen) {
    extern __shared__ __half smh[];
    const int tid = threadIdx.x;
    const int wid = tid >> 5, lid = tid & 31;
    const int gid = lid >> 2, tig = lid & 3;
    const int wm = wid >> 2, wn = wid & 3;
    const int m0 = blockIdx.y * 128;
    const int n0 = blockIdx.x * 128;
    const int kbase = blockIdx.z * Klen;
    const int T = Klen >> 5;

    float acc[4][4][4];
    #pragma unroll
    for (int i = 0; i < 4; i++)
        #pragma unroll
        for (int j = 0; j < 4; j++)
            #pragma unroll
            for (int c = 0; c < 4; c++) acc[i][j][c] = 0.f;

    const uint32_t smb = smem_u32(smh);
    const int lg = lid >> 3, r8 = lid & 7;
    const uint32_t aoff = ((uint32_t)(wm * 64 + (lg & 1) * 8 + r8) * HPITCH
                           + (lg >> 1) * 8) * 2;
    const uint32_t boff = ((uint32_t)(wn * 32 + (lg >> 1) * 8 + r8) * HPITCH
                           + (lg & 1) * 8) * 2 + (uint32_t)TILEH * 2;

    auto load_tiles = [&](int buf, int k0) {
        uint32_t base = smb + (uint32_t)buf * (BUFFH * 2);
        #pragma unroll
        for (int t = 0; t < 2; t++) {
            int c = tid + t * 256;
            int row = c >> 2;
            int ch = (c & 3) * 8;
            uint32_t soff = (uint32_t)row * (HPITCH * 2) + ch * 2;
            CP_ASYNC16(base + soff,
                       A + (size_t)(m0 + row) * Kstride + kbase + k0 + ch);
            CP_ASYNC16(base + (uint32_t)TILEH * 2 + soff,
                       W + (size_t)(n0 + row) * Kstride + kbase + k0 + ch);
        }
    };

    load_tiles(0, 0);
    CP_COMMIT();
    load_tiles(1, 32);
    CP_COMMIT();

    int stage = 0;
    for (int i = 0; i < T; i++) {
        if (i < T - 1) cp_wait<1>(); else cp_wait<0>();
        __syncthreads();
        if (i + 2 < T) {
            int nst = stage + 2; if (nst >= 3) nst -= 3;
            load_tiles(nst, (i + 2) << 5);
            CP_COMMIT();
        }

        const uint32_t base = smb + (uint32_t)stage * (BUFFH * 2);
        #pragma unroll
        for (int kh = 0; kh < 2; kh++) {
            const uint32_t kso = (uint32_t)kh * 32;
            uint32_t a[4][4], bb[2][4];
            #pragma unroll
            for (int mi = 0; mi < 4; mi++)
                ldsm_x4(base + aoff + (uint32_t)(mi * 16 * HPITCH) * 2 + kso, a[mi]);
            #pragma unroll
            for (int p = 0; p < 2; p++)
                ldsm_x4(base + boff + (uint32_t)(p * 16 * HPITCH) * 2 + kso, bb[p]);
            #pragma unroll
            for (int mi = 0; mi < 4; mi++) {
                mma_f16(acc[mi][0], a[mi], bb[0]);
                mma_f16(acc[mi][1], a[mi], bb[0] + 2);
                mma_f16(acc[mi][2], a[mi], bb[1]);
                mma_f16(acc[mi][3], a[mi], bb[1] + 2);
            }
        }
        stage = (stage + 1 == 3) ? 0 : stage + 1;
    }

    #pragma unroll
    for (int mi = 0; mi < 4; mi++) {
        const int mA = m0 + wm * 64 + mi * 16 + gid;
        const int mB = mA + 8;
        #pragma unroll
        for (int nj = 0; nj < 4; nj++) {
            const int col = n0 + wn * 32 + nj * 8 + tig * 2;
            float2 v0 = make_float2(acc[mi][nj][0], acc[mi][nj][1]);
            float2 v1 = make_float2(acc[mi][nj][2], acc[mi][nj][3]);
            if (EPI == 1 || EPI == 5) {
                if (EPI == 1) {
                    v0.x = fmaxf(v0.x, 0.f); v0.y = fmaxf(v0.y, 0.f);
                    v1.x = fmaxf(v1.x, 0.f); v1.y = fmaxf(v1.y, 0.f);
                }
                *(__half2*)((__half*)C + (size_t)mA * Nc + col) =
                    __floats2half2_rn(v0.x, v0.y);
                *(__half2*)((__half*)C + (size_t)mB * Nc + col) =
                    __floats2half2_rn(v1.x, v1.y);
            } else {  // EPI == 3
                float* c0 = (float*)C + (size_t)mA * Nc + col;
                float* c1 = (float*)C + (size_t)mB * Nc + col;
                atomicAdd(c0, v0.x); atomicAdd(c0 + 1, v0.y);
                atomicAdd(c1, v1.x); atomicAdd(c1 + 1, v1.y);
            }
        }
    }
}

// ---------------- fp16 flash attention: q-tile 128, 8 warps ------------------
// Pitch 72 halves (144 B) everywhere -> conflict-free ldmatrix/stores.
#define AQP 72
#define QBUF  (128 * AQP)
#define KBUFH (64 * AQP)
#define VBUFH (64 * AQP)
#define PBUF  (128 * AQP)
#define KOFF(b)  (QBUF + (b) * KBUFH)
#define VOFF(b)  (QBUF + 2 * KBUFH + (b) * VBUFH)
#define POFF     (QBUF + 2 * KBUFH + 2 * VBUFH)
#define ATT_SMEM ((QBUF + 2 * KBUFH + 2 * VBUFH + PBUF) * 2)  // 73728 B

__global__ __launch_bounds__(256, 2)
void attention_f16_kernel(const __half* __restrict__ QKV,
                          const float* __restrict__ tab,
                          __half* __restrict__ O) {
    extern __shared__ __half smha[];
    const int bh = blockIdx.y;
    const int b = bh >> 4, h = bh & 15;
    const int q0 = blockIdx.x * 128;
    const int tid = threadIdx.x;
    const int wid = tid >> 5, lid = tid & 31;
    const int gid = lid >> 2, tig = lid & 3;
    const int lg = lid >> 3, r8 = lid & 7;
    const uint32_t smb = smem_u32(smha);

    // ldmatrix lane addresses (bytes)
    const uint32_t qa = smb + ((uint32_t)(wid * 16 + (lg & 1) * 8 + r8) * AQP
                               + (lg >> 1) * 8) * 2;
    const uint32_t ka = ((uint32_t)((lg >> 1) * 8 + r8) * AQP + (lg & 1) * 8) * 2;
    const uint32_t va = ((uint32_t)((lg & 1) * 8 + r8) * AQP + (lg >> 1) * 8) * 2;
    const uint32_t pa = smb + ((uint32_t)POFF + (uint32_t)(wid * 16 + (lg & 1) * 8 + r8) * AQP
                               + (lg >> 1) * 8) * 2;

    auto load_q = [&]() {
        #pragma unroll
        for (int t = 0; t < 4; t++) {
            int c = tid + t * 256;              // 0..1023
            int row = c >> 3, ch = (c & 7) * 8;
            CP_ASYNC16(smb + ((uint32_t)row * AQP + ch) * 2,
                       QKV + (size_t)(b * SEQ + q0 + row) * QKV_N + h * D_KV + ch);
        }
    };
    auto load_kv = [&](int buf, int k0) {
        #pragma unroll
        for (int t = 0; t < 2; t++) {
            int c = tid + t * 256;              // 0..511
            int row = c >> 3, ch = (c & 7) * 8;
            size_t g = (size_t)(b * SEQ + k0 + row) * QKV_N + h * D_KV + ch;
            CP_ASYNC16(smb + ((uint32_t)KOFF(buf) + (uint32_t)row * AQP + ch) * 2,
                       QKV + INNER + g);
            CP_ASYNC16(smb + ((uint32_t)VOFF(buf) + (uint32_t)row * AQP + ch) * 2,
                       QKV + 2 * INNER + g);
        }
    };

    float oacc[8][4];
    #pragma unroll
    for (int nj = 0; nj < 8; nj++)
        #pragma unroll
        for (int c = 0; c < 4; c++) oacc[nj][c] = 0.f;
    float m0 = -1e30f, m1 = -1e30f, l0 = 0.f, l1 = 0.f;
    uint32_t qf[4][4];

    load_q();
    load_kv(0, 0);
    CP_COMMIT();

    for (int it = 0; it < SEQ / 64; it++) {
        const int cur = it & 1;
        const int k0 = it * 64;
        cp_wait<0>();
        __syncthreads();
        if (it + 1 < SEQ / 64) {
            load_kv(cur ^ 1, k0 + 64);
            CP_COMMIT();
        }
        if (it == 0) {
            #pragma unroll
            for (int ks = 0; ks < 4; ks++)
                ldsm_x4(qa + (uint32_t)ks * 32, qf[ks]);
        }
        const uint32_t kb = smb + (uint32_t)KOFF(cur) * 2 + ka;
        const uint32_t vb = smb + (uint32_t)VOFF(cur) * 2 + va;

        // S = Q @ K^T
        float sacc[8][4];
        #pragma unroll
        for (int nj = 0; nj < 8; nj++)
            #pragma unroll
            for (int c = 0; c < 4; c++) sacc[nj][c] = 0.f;
        #pragma unroll
        for (int ks = 0; ks < 4; ks++) {
            const uint32_t kso = (uint32_t)ks * 32;
            #pragma unroll
            for (int p = 0; p < 4; p++) {
                uint32_t bb[4];
                ldsm_x4(kb + (uint32_t)(p * 16 * AQP) * 2 + kso, bb);
                mma_f16(sacc[2 * p], qf[ks], bb);
                mma_f16(sacc[2 * p + 1], qf[ks], bb + 2);
            }
        }

        // bias + online softmax (rows gid / gid+8)
        const float* bt = tab + h * TAB_LEN + 1023 + k0 - (q0 + wid * 16);
        float rx0 = -1e30f, rx1 = -1e30f;
        #pragma unroll
        for (int nj = 0; nj < 8; nj++) {
            int c = nj * 8 + 2 * tig;
            sacc[nj][0] += __ldg(bt + c - gid);
            sacc[nj][1] += __ldg(bt + c + 1 - gid);
            sacc[nj][2] += __ldg(bt + c - gid - 8);
            sacc[nj][3] += __ldg(bt + c + 1 - gid - 8);
            rx0 = fmaxf(rx0, fmaxf(sacc[nj][0], sacc[nj][1]));
            rx1 = fmaxf(rx1, fmaxf(sacc[nj][2], sacc[nj][3]));
        }
        rx0 = fmaxf(rx0, __shfl_xor_sync(0xFFFFFFFFu, rx0, 1));
        rx0 = fmaxf(rx0, __shfl_xor_sync(0xFFFFFFFFu, rx0, 2));
        rx1 = fmaxf(rx1, __shfl_xor_sync(0xFFFFFFFFu, rx1, 1));
        rx1 = fmaxf(rx1, __shfl_xor_sync(0xFFFFFFFFu, rx1, 2));
        float mn0 = fmaxf(m0, rx0), mn1 = fmaxf(m1, rx1);
        float sc0 = __expf(m0 - mn0), sc1 = __expf(m1 - mn1);
        m0 = mn0; m1 = mn1;

        float rs0 = 0.f, rs1 = 0.f;
        __half* pr0 = smha + POFF + (wid * 16 + gid) * AQP;
        __half* pr1 = pr0 + 8 * AQP;
        #pragma unroll
        for (int nj = 0; nj < 8; nj++) {
            int c = nj * 8 + 2 * tig;
            float p0 = __expf(sacc[nj][0] - m0);
            float p1 = __expf(sacc[nj][1] - m0);
            float p2 = __expf(sacc[nj][2] - m1);
            float p3 = __expf(sacc[nj][3] - m1);
            rs0 += p0 + p1; rs1 += p2 + p3;
            *(__half2*)(pr0 + c) = __floats2half2_rn(p0, p1);
            *(__half2*)(pr1 + c) = __floats2half2_rn(p2, p3);
        }
        rs0 += __shfl_xor_sync(0xFFFFFFFFu, rs0, 1);
        rs0 += __shfl_xor_sync(0xFFFFFFFFu, rs0, 2);
        rs1 += __shfl_xor_sync(0xFFFFFFFFu, rs1, 1);
        rs1 += __shfl_xor_sync(0xFFFFFFFFu, rs1, 2);
        l0 = l0 * sc0 + rs0;
        l1 = l1 * sc1 + rs1;
        #pragma unroll
        for (int nj = 0; nj < 8; nj++) {
            oacc[nj][0] *= sc0; oacc[nj][1] *= sc0;
            oacc[nj][2] *= sc1; oacc[nj][3] *= sc1;
        }
        __syncwarp();

        // O += P @ V (P non-trans A-frags, V trans B-frags)
        #pragma unroll
        for (int ks = 0; ks < 4; ks++) {
            uint32_t af[4];
            ldsm_x4(pa + (uint32_t)ks * 32, af);
            #pragma unroll
            for (int p = 0; p < 4; p++) {
                uint32_t bb[4];
                ldsm_x4_t(vb + (uint32_t)(ks * 16 * AQP) * 2 + (uint32_t)p * 32, bb);
                mma_f16(oacc[2 * p], af, bb);
                mma_f16(oacc[2 * p + 1], af, bb + 2);
            }
        }
    }

    float i0 = 1.f / l0, i1 = 1.f / l1;
    __half* ob = O + (size_t)(b * SEQ + q0 + wid * 16 + gid) * INNER + h * D_KV;
    #pragma unroll
    for (int nj = 0; nj < 8; nj++) {
        int c = nj * 8 + 2 * tig;
        *(__half2*)(ob + c) = __floats2half2_rn(oacc[nj][0] * i0, oacc[nj][1] * i0);
        *(__half2*)(ob + 8 * INNER + c) =
            __floats2half2_rn(oacc[nj][2] * i1, oacc[nj][3] * i1);
    }
}

// ---------------- launch -----------------------------------------------------
extern "C" void kernel_launch(void* const* d_in, const int* in_sizes, int n_in,
                              void* d_out, int out_size) {
    const float* hidden  = (const float*)d_in[0];
    const float* ln1_w   = (const float*)d_in[1];
    const float* wq      = (const float*)d_in[2];
    const float* wk      = (const float*)d_in[3];
    const float* wv      = (const float*)d_in[4];
    const float* wo      = (const float*)d_in[5];
    const float* relbias = (const float*)d_in[6];
    const float* ln2_w   = (const float*)d_in[7];
    const float* wi      = (const float*)d_in[8];
    const float* wo_ff   = (const float*)d_in[9];
    float* out = (float*)d_out;

    __half *px, *pqkv, *pctx, *py, *pmid;
    float *ph, *pbias;
    __half *pwqkv, *pwo, *pwi, *pwoff;
    cudaGetSymbolAddress((void**)&px,    g_x);
    cudaGetSymbolAddress((void**)&pqkv,  g_qkv);
    cudaGetSymbolAddress((void**)&pctx,  g_ctx);
    cudaGetSymbolAddress((void**)&ph,    g_h);
    cudaGetSymbolAddress((void**)&py,    g_y);
    cudaGetSymbolAddress((void**)&pmid,  g_mid);
    cudaGetSymbolAddress((void**)&pbias, g_bias);
    cudaGetSymbolAddress((void**)&pwqkv, g_wqkv_h);
    cudaGetSymbolAddress((void**)&pwo,   g_wo_h);
    cudaGetSymbolAddress((void**)&pwi,   g_wi_h);
    cudaGetSymbolAddress((void**)&pwoff, g_woff_h);

    cudaFuncSetAttribute((gemm_f16_kernel<1, __half>), cudaFuncAttributeMaxDynamicSharedMemorySize, GEMM_SMEM);
    cudaFuncSetAttribute((gemm_f16_kernel<3, float>),  cudaFuncAttributeMaxDynamicSharedMemorySize, GEMM_SMEM);
    cudaFuncSetAttribute((gemm_f16_kernel<5, __half>), cudaFuncAttributeMaxDynamicSharedMemorySize, GEMM_SMEM);
    cudaFuncSetAttribute(attention_f16_kernel, cudaFuncAttributeMaxDynamicSharedMemorySize, ATT_SMEM);

    // 0: fused weight conversion to fp16
    convert_all_kernel<<<(N4TOT + 255) / 256, 256>>>(
        (const float4*)wq, (const float4*)wk, (const float4*)wv,
        (const float4*)wo, (const float4*)wi, (const float4*)wo_ff,
        pwqkv, pwo, pwi, pwoff);

    // 1,2
    bias_table_kernel<<<(TAB_LEN + 255) / 256, 256>>>(relbias, pbias);
    rmsnorm_kernel<<<M_ROWS, 256>>>(hidden, ln1_w, px);

    // 3: QKV projection -> fp16 qkv
    gemm_f16_kernel<5, __half><<<dim3(QKV_N / 128, M_ROWS / 128), 256, GEMM_SMEM>>>(
        px, pwqkv, pqkv, M_ROWS, QKV_N, D_MODEL, D_MODEL);

    // 4: fp16 attention (q-tile 128, 8 warps) -> fp16 ctx
    attention_f16_kernel<<<dim3(SEQ / 128, BATCH * N_HEADS), 256, ATT_SMEM>>>(
        pqkv, pbias, pctx);

    // 5: h = hidden + ctx @ wo^T (split-K2 atomic)
    cudaMemcpyAsync(ph, hidden, (size_t)M_ROWS * D_MODEL * sizeof(float),
                    cudaMemcpyDeviceToDevice);
    gemm_f16_kernel<3, float><<<dim3(D_MODEL / 128, M_ROWS / 128, 2), 256, GEMM_SMEM>>>(
        pctx, pwo, ph, M_ROWS, D_MODEL, INNER, INNER / 2);

    // 6
    rmsnorm_kernel<<<M_ROWS, 256>>>(ph, ln2_w, py);

    // 7: mid = relu(y @ wi^T) -> fp16
    gemm_f16_kernel<1, __half><<<dim3(D_FF / 128, M_ROWS / 128), 256, GEMM_SMEM>>>(
        py, pwi, pmid, M_ROWS, D_FF, D_MODEL, D_MODEL);

    // 8: out = h + mid @ wo_ff^T (split-K2 atomic)
    cudaMemcpyAsync(out, ph, (size_t)M_ROWS * D_MODEL * sizeof(float),
                    cudaMemcpyDeviceToDevice);
    gemm_f16_kernel<3, float><<<dim3(D_MODEL / 128, M_ROWS / 128, 2), 256, GEMM_SMEM>>>(
        pmid, pwoff, out, M_ROWS, D_MODEL, D_FF, D_FF / 2);
}